// round 2
// baseline (speedup 1.0000x reference)
#include <cuda_runtime.h>
#include <math.h>

// ---------------------------------------------------------------------------
// Problem constants
// ---------------------------------------------------------------------------
#define D_MODEL 1024
#define T_LEN   2048
#define BATCH   2
#define N_HEADS 16
#define D_HEAD  64
#define BT      (BATCH * T_LEN)          // 4096 rows
#define W_ELEMS (D_MODEL * D_MODEL)      // 1048576

// ---------------------------------------------------------------------------
// Scratch (static device memory; no runtime allocation allowed)
// ---------------------------------------------------------------------------
__device__ float  g_Wt[4][W_ELEMS];                  // ternarized weights (alpha folded in)
__device__ float  g_Q[BT * D_MODEL];
__device__ float  g_K[BT * D_MODEL];
__device__ float  g_V[BT * D_MODEL];
__device__ float  g_O[BT * D_MODEL];                 // attention output
__device__ float  g_Y[BT * D_MODEL];                 // pre-quant final
__device__ float  g_S[(size_t)BATCH * N_HEADS * T_LEN * T_LEN]; // 512 MB scores
__device__ double g_red[4][1024];
__device__ double g_red2a[4][1024];
__device__ double g_red2b[4][1024];
__device__ float  g_delta[4];
__device__ float  g_alpha[4];
__device__ float  g_maxp[4096];
__device__ float  g_scale;

// ---------------------------------------------------------------------------
// Weight ternarization statistics
// ---------------------------------------------------------------------------
__device__ __forceinline__ const float* pick_w(const float* W0, const float* W1,
                                               const float* W2, const float* W3, int y) {
    return y == 0 ? W0 : (y == 1 ? W1 : (y == 2 ? W2 : W3));
}

__global__ void k_wabs(const float* __restrict__ W0, const float* __restrict__ W1,
                       const float* __restrict__ W2, const float* __restrict__ W3) {
    const float* W = pick_w(W0, W1, W2, W3, blockIdx.y);
    __shared__ double sm[256];
    int base = blockIdx.x * 1024;
    double s = 0.0;
    for (int i = threadIdx.x; i < 1024; i += 256)
        s += (double)fabsf(W[base + i]);
    sm[threadIdx.x] = s;
    __syncthreads();
    for (int st = 128; st > 0; st >>= 1) {
        if (threadIdx.x < st) sm[threadIdx.x] += sm[threadIdx.x + st];
        __syncthreads();
    }
    if (threadIdx.x == 0) g_red[blockIdx.y][blockIdx.x] = sm[0];
}

__global__ void k_wstat1() {
    __shared__ double sm[256];
    double s = 0.0;
    for (int i = threadIdx.x; i < 1024; i += 256) s += g_red[blockIdx.x][i];
    sm[threadIdx.x] = s;
    __syncthreads();
    for (int st = 128; st > 0; st >>= 1) {
        if (threadIdx.x < st) sm[threadIdx.x] += sm[threadIdx.x + st];
        __syncthreads();
    }
    if (threadIdx.x == 0)
        g_delta[blockIdx.x] = (float)(0.05 * (sm[0] / (double)W_ELEMS));
}

__global__ void k_wmask(const float* __restrict__ W0, const float* __restrict__ W1,
                        const float* __restrict__ W2, const float* __restrict__ W3) {
    const float* W = pick_w(W0, W1, W2, W3, blockIdx.y);
    float delta = g_delta[blockIdx.y];
    __shared__ double sa[256];
    __shared__ double sb[256];
    int base = blockIdx.x * 1024;
    double s1 = 0.0, s2 = 0.0;
    for (int i = threadIdx.x; i < 1024; i += 256) {
        float a = fabsf(W[base + i]);
        if (a > delta) { s1 += (double)a; s2 += 1.0; }
    }
    sa[threadIdx.x] = s1; sb[threadIdx.x] = s2;
    __syncthreads();
    for (int st = 128; st > 0; st >>= 1) {
        if (threadIdx.x < st) {
            sa[threadIdx.x] += sa[threadIdx.x + st];
            sb[threadIdx.x] += sb[threadIdx.x + st];
        }
        __syncthreads();
    }
    if (threadIdx.x == 0) {
        g_red2a[blockIdx.y][blockIdx.x] = sa[0];
        g_red2b[blockIdx.y][blockIdx.x] = sb[0];
    }
}

__global__ void k_wstat2() {
    __shared__ double sa[256];
    __shared__ double sb[256];
    double s1 = 0.0, s2 = 0.0;
    for (int i = threadIdx.x; i < 1024; i += 256) {
        s1 += g_red2a[blockIdx.x][i];
        s2 += g_red2b[blockIdx.x][i];
    }
    sa[threadIdx.x] = s1; sb[threadIdx.x] = s2;
    __syncthreads();
    for (int st = 128; st > 0; st >>= 1) {
        if (threadIdx.x < st) {
            sa[threadIdx.x] += sa[threadIdx.x + st];
            sb[threadIdx.x] += sb[threadIdx.x + st];
        }
        __syncthreads();
    }
    if (threadIdx.x == 0)
        g_alpha[blockIdx.x] = (float)(sa[0] / fmax(sb[0], 1.0));
}

__global__ void k_wtern(const float* __restrict__ W0, const float* __restrict__ W1,
                        const float* __restrict__ W2, const float* __restrict__ W3) {
    int y = blockIdx.y;
    const float* W = pick_w(W0, W1, W2, W3, y);
    float delta = g_delta[y];
    float alpha = g_alpha[y];
    int i = blockIdx.x * 1024 + threadIdx.x;
    float w = W[i];
    float a = fabsf(w);
    float t = 0.0f;
    if (a > delta) t = (w > 0.0f) ? alpha : -alpha;
    g_Wt[y][i] = t;
}

// ---------------------------------------------------------------------------
// SGEMM NT:  C[m][n] = scale * sum_k A[m][k] * B[n][k]  (+ bias[n])
// Tiles: BM=128, BN=128, BK=16, 256 threads, 8x8 micro-tile (split 4+4).
// z decomposes as (zb, zh) = (z>>4, z&15) for batched per-head launches.
// ---------------------------------------------------------------------------
__global__ void __launch_bounds__(256)
k_gemm_nt(const float* __restrict__ A, int lda, size_t sAb, size_t sAh,
          const float* __restrict__ B, int ldb, size_t sBb, size_t sBh,
          float* __restrict__ C, int ldc, size_t sCb, size_t sCh,
          const float* __restrict__ bias, float scale, int K) {
    int z = blockIdx.z, zb = z >> 4, zh = z & 15;
    A += (size_t)zb * sAb + (size_t)zh * sAh;
    B += (size_t)zb * sBb + (size_t)zh * sBh;
    C += (size_t)zb * sCb + (size_t)zh * sCh;

    __shared__ float As[16][128];
    __shared__ float Bs[16][128];

    int tid = threadIdx.x;
    int ty = tid >> 4, tx = tid & 15;
    int rowBase = blockIdx.x * 128;
    int colBase = blockIdx.y * 128;

    float acc[8][8];
#pragma unroll
    for (int i = 0; i < 8; i++)
#pragma unroll
        for (int j = 0; j < 8; j++) acc[i][j] = 0.0f;

    for (int k0 = 0; k0 < K; k0 += 16) {
#pragma unroll
        for (int l = 0; l < 2; l++) {
            int f = tid + l * 256;          // 0..511
            int row = f >> 2;               // 0..127
            int kq = f & 3;                 // float4 slot
            float4 va = *(const float4*)(A + (size_t)(rowBase + row) * lda + k0 + kq * 4);
            As[kq * 4 + 0][row] = va.x;
            As[kq * 4 + 1][row] = va.y;
            As[kq * 4 + 2][row] = va.z;
            As[kq * 4 + 3][row] = va.w;
            float4 vb = *(const float4*)(B + (size_t)(colBase + row) * ldb + k0 + kq * 4);
            Bs[kq * 4 + 0][row] = vb.x;
            Bs[kq * 4 + 1][row] = vb.y;
            Bs[kq * 4 + 2][row] = vb.z;
            Bs[kq * 4 + 3][row] = vb.w;
        }
        __syncthreads();
#pragma unroll
        for (int kk = 0; kk < 16; kk++) {
            float4 a0 = *(const float4*)&As[kk][ty * 4];
            float4 a1 = *(const float4*)&As[kk][64 + ty * 4];
            float4 b0 = *(const float4*)&Bs[kk][tx * 4];
            float4 b1 = *(const float4*)&Bs[kk][64 + tx * 4];
            float ar[8] = {a0.x, a0.y, a0.z, a0.w, a1.x, a1.y, a1.z, a1.w};
            float br[8] = {b0.x, b0.y, b0.z, b0.w, b1.x, b1.y, b1.z, b1.w};
#pragma unroll
            for (int i = 0; i < 8; i++)
#pragma unroll
                for (int j = 0; j < 8; j++)
                    acc[i][j] = fmaf(ar[i], br[j], acc[i][j]);
        }
        __syncthreads();
    }

#pragma unroll
    for (int i = 0; i < 8; i++) {
        int r = rowBase + ((i < 4) ? (ty * 4 + i) : (64 + ty * 4 + i - 4));
        float bb[8];
#pragma unroll
        for (int j = 0; j < 8; j++) {
            int c = colBase + ((j < 4) ? (tx * 4 + j) : (64 + tx * 4 + j - 4));
            bb[j] = bias ? bias[c] : 0.0f;
        }
        float4 v0 = make_float4(acc[i][0] * scale + bb[0], acc[i][1] * scale + bb[1],
                                acc[i][2] * scale + bb[2], acc[i][3] * scale + bb[3]);
        float4 v1 = make_float4(acc[i][4] * scale + bb[4], acc[i][5] * scale + bb[5],
                                acc[i][6] * scale + bb[6], acc[i][7] * scale + bb[7]);
        *(float4*)(C + (size_t)r * ldc + colBase + tx * 4) = v0;
        *(float4*)(C + (size_t)r * ldc + colBase + 64 + tx * 4) = v1;
    }
}

// ---------------------------------------------------------------------------
// SGEMM NN:  C[m][n] = sum_k A[m][k] * B[k][n]   (BM=128, BN=64, BK=16)
// Used for O = P @ V (N = Dh = 64).
// ---------------------------------------------------------------------------
__global__ void __launch_bounds__(256)
k_gemm_nn(const float* __restrict__ A, int lda, size_t sAb, size_t sAh,
          const float* __restrict__ B, int ldb, size_t sBb, size_t sBh,
          float* __restrict__ C, int ldc, size_t sCb, size_t sCh, int K) {
    int z = blockIdx.z, zb = z >> 4, zh = z & 15;
    A += (size_t)zb * sAb + (size_t)zh * sAh;
    B += (size_t)zb * sBb + (size_t)zh * sBh;
    C += (size_t)zb * sCb + (size_t)zh * sCh;

    __shared__ float As[16][128];
    __shared__ float Bs[16][64];

    int tid = threadIdx.x;
    int ty = tid >> 4, tx = tid & 15;
    int rowBase = blockIdx.x * 128;

    float acc[8][4];
#pragma unroll
    for (int i = 0; i < 8; i++)
#pragma unroll
        for (int j = 0; j < 4; j++) acc[i][j] = 0.0f;

    for (int k0 = 0; k0 < K; k0 += 16) {
#pragma unroll
        for (int l = 0; l < 2; l++) {
            int f = tid + l * 256;
            int row = f >> 2;
            int kq = f & 3;
            float4 va = *(const float4*)(A + (size_t)(rowBase + row) * lda + k0 + kq * 4);
            As[kq * 4 + 0][row] = va.x;
            As[kq * 4 + 1][row] = va.y;
            As[kq * 4 + 2][row] = va.z;
            As[kq * 4 + 3][row] = va.w;
        }
        {
            int krow = tid >> 4;   // 0..15
            int n4 = tid & 15;     // 0..15 -> 4-float chunk
            float4 vb = *(const float4*)(B + (size_t)(k0 + krow) * ldb + n4 * 4);
            *(float4*)&Bs[krow][n4 * 4] = vb;
        }
        __syncthreads();
#pragma unroll
        for (int kk = 0; kk < 16; kk++) {
            float4 a0 = *(const float4*)&As[kk][ty * 4];
            float4 a1 = *(const float4*)&As[kk][64 + ty * 4];
            float4 b = *(const float4*)&Bs[kk][tx * 4];
            float ar[8] = {a0.x, a0.y, a0.z, a0.w, a1.x, a1.y, a1.z, a1.w};
            float br[4] = {b.x, b.y, b.z, b.w};
#pragma unroll
            for (int i = 0; i < 8; i++)
#pragma unroll
                for (int j = 0; j < 4; j++)
                    acc[i][j] = fmaf(ar[i], br[j], acc[i][j]);
        }
        __syncthreads();
    }

#pragma unroll
    for (int i = 0; i < 8; i++) {
        int r = rowBase + ((i < 4) ? (ty * 4 + i) : (64 + ty * 4 + i - 4));
        float4 v = make_float4(acc[i][0], acc[i][1], acc[i][2], acc[i][3]);
        *(float4*)(C + (size_t)r * ldc + tx * 4) = v;
    }
}

// ---------------------------------------------------------------------------
// Row softmax over rows of length 2048 (in place), exact two-pass like jax.
// ---------------------------------------------------------------------------
__global__ void k_softmax(float* __restrict__ S) {
    size_t row = blockIdx.x;
    float* p = S + row * (size_t)T_LEN;
    __shared__ float sm[256];
    int tid = threadIdx.x;

    float v[8];
    float m = -INFINITY;
#pragma unroll
    for (int i = 0; i < 8; i++) {
        v[i] = p[tid + i * 256];
        m = fmaxf(m, v[i]);
    }
    sm[tid] = m;
    __syncthreads();
    for (int st = 128; st > 0; st >>= 1) {
        if (tid < st) sm[tid] = fmaxf(sm[tid], sm[tid + st]);
        __syncthreads();
    }
    m = sm[0];
    __syncthreads();

    float s = 0.0f;
#pragma unroll
    for (int i = 0; i < 8; i++) {
        v[i] = expf(v[i] - m);
        s += v[i];
    }
    sm[tid] = s;
    __syncthreads();
    for (int st = 128; st > 0; st >>= 1) {
        if (tid < st) sm[tid] += sm[tid + st];
        __syncthreads();
    }
    float total = sm[0];
#pragma unroll
    for (int i = 0; i < 8; i++)
        p[tid + i * 256] = v[i] / total;
}

// ---------------------------------------------------------------------------
// fp4 activation quant: scale = max(max|y| / 7, 1e-8); q = clip(rint(y/s)) * s
// ---------------------------------------------------------------------------
__global__ void k_absmax_partial(const float* __restrict__ Y) {
    __shared__ float sm[256];
    int base = blockIdx.x * 1024;
    int tid = threadIdx.x;
    float m = 0.0f;
#pragma unroll
    for (int i = 0; i < 4; i++)
        m = fmaxf(m, fabsf(Y[base + tid + i * 256]));
    sm[tid] = m;
    __syncthreads();
    for (int st = 128; st > 0; st >>= 1) {
        if (tid < st) sm[tid] = fmaxf(sm[tid], sm[tid + st]);
        __syncthreads();
    }
    if (tid == 0) g_maxp[blockIdx.x] = sm[0];
}

__global__ void k_absmax_final() {
    __shared__ float sm[1024];
    int tid = threadIdx.x;
    float m = 0.0f;
#pragma unroll
    for (int i = 0; i < 4; i++)
        m = fmaxf(m, g_maxp[tid + i * 1024]);
    sm[tid] = m;
    __syncthreads();
    for (int st = 512; st > 0; st >>= 1) {
        if (tid < st) sm[tid] = fmaxf(sm[tid], sm[tid + st]);
        __syncthreads();
    }
    if (tid == 0) g_scale = fmaxf(sm[0] / 7.0f, 1e-8f);
}

__global__ void k_quant(const float* __restrict__ Y, float* __restrict__ out) {
    int i = blockIdx.x * 1024 + threadIdx.x;
    float s = g_scale;
    float q = rintf(Y[i] / s);
    q = fminf(7.0f, fmaxf(-7.0f, q));
    out[i] = q * s;
}

// ---------------------------------------------------------------------------
// Launch
// ---------------------------------------------------------------------------
extern "C" void kernel_launch(void* const* d_in, const int* in_sizes, int n_in,
                              void* d_out, int out_size) {
    const float* x  = (const float*)d_in[0];
    const float* Wq = (const float*)d_in[1];
    const float* bq = (const float*)d_in[2];
    const float* Wk = (const float*)d_in[3];
    const float* bk = (const float*)d_in[4];
    const float* Wv = (const float*)d_in[5];
    const float* bv = (const float*)d_in[6];
    const float* Wo = (const float*)d_in[7];
    const float* bo = (const float*)d_in[8];
    float* out = (float*)d_out;

    // Resolve device scratch addresses (host-side symbol addresses of __device__ arrays)
    float* wt0; cudaGetSymbolAddress((void**)&wt0, g_Wt);
    float* wt1 = wt0 + (size_t)1 * W_ELEMS;
    float* wt2 = wt0 + (size_t)2 * W_ELEMS;
    float* wt3 = wt0 + (size_t)3 * W_ELEMS;
    float* q;  cudaGetSymbolAddress((void**)&q,  g_Q);
    float* k;  cudaGetSymbolAddress((void**)&k,  g_K);
    float* v;  cudaGetSymbolAddress((void**)&v,  g_V);
    float* o;  cudaGetSymbolAddress((void**)&o,  g_O);
    float* y;  cudaGetSymbolAddress((void**)&y,  g_Y);
    float* s;  cudaGetSymbolAddress((void**)&s,  g_S);

    // 1) Weight ternarization statistics
    k_wabs<<<dim3(1024, 4), 256>>>(Wq, Wk, Wv, Wo);
    k_wstat1<<<4, 256>>>();
    k_wmask<<<dim3(1024, 4), 256>>>(Wq, Wk, Wv, Wo);
    k_wstat2<<<4, 256>>>();
    k_wtern<<<dim3(1024, 4), 1024>>>(Wq, Wk, Wv, Wo);

    // 2) Projections: Q/K/V = x @ Wt^T + b   (M=4096, N=1024, K=1024)
    k_gemm_nt<<<dim3(32, 8, 1), 256>>>(x, D_MODEL, 0, 0,
                                       wt0, D_MODEL, 0, 0,
                                       q, D_MODEL, 0, 0, bq, 1.0f, D_MODEL);
    k_gemm_nt<<<dim3(32, 8, 1), 256>>>(x, D_MODEL, 0, 0,
                                       wt1, D_MODEL, 0, 0,
                                       k, D_MODEL, 0, 0, bk, 1.0f, D_MODEL);
    k_gemm_nt<<<dim3(32, 8, 1), 256>>>(x, D_MODEL, 0, 0,
                                       wt2, D_MODEL, 0, 0,
                                       v, D_MODEL, 0, 0, bv, 1.0f, D_MODEL);

    // 3) Scores: S[b,h] = (Q_bh @ K_bh^T) * 0.125   (M=N=2048, K=64, 32 batches)
    const size_t sQb = (size_t)T_LEN * D_MODEL;   // batch stride in Q/K/V/O
    const size_t sQh = (size_t)D_HEAD;            // head stride
    const size_t sSh = (size_t)T_LEN * T_LEN;     // head stride in S
    const size_t sSb = (size_t)N_HEADS * sSh;     // batch stride in S
    k_gemm_nt<<<dim3(16, 16, BATCH * N_HEADS), 256>>>(
        q, D_MODEL, sQb, sQh,
        k, D_MODEL, sQb, sQh,
        s, T_LEN, sSb, sSh, nullptr, 0.125f, D_HEAD);

    // 4) Softmax over rows of S
    k_softmax<<<BATCH * N_HEADS * T_LEN, 256>>>(s);

    // 5) O[b,h] = P @ V   (M=2048, N=64, K=2048)
    k_gemm_nn<<<dim3(16, 1, BATCH * N_HEADS), 256>>>(
        s, T_LEN, sSb, sSh,
        v, D_MODEL, sQb, sQh,
        o, D_MODEL, sQb, sQh, T_LEN);

    // 6) Output projection: Y = O @ Wt_o^T + bo
    k_gemm_nt<<<dim3(32, 8, 1), 256>>>(o, D_MODEL, 0, 0,
                                       wt3, D_MODEL, 0, 0,
                                       y, D_MODEL, 0, 0, bo, 1.0f, D_MODEL);

    // 7) fp4 activation quant -> d_out
    k_absmax_partial<<<4096, 256>>>(y);
    k_absmax_final<<<1, 1024>>>();
    k_quant<<<4096, 1024>>>(y, out);
}

// round 8
// speedup vs baseline: 1.1793x; 1.1793x over previous
#include <cuda_runtime.h>
#include <cuda_fp16.h>
#include <math.h>
#include <stdint.h>

#define D_MODEL 1024
#define T_LEN   2048
#define BATCH   2
#define N_HEADS 16
#define D_HEAD  64
#define BT      (BATCH * T_LEN)
#define W_ELEMS (D_MODEL * D_MODEL)

#define SPLIT_UP   2048.0f          // 2^11
#define SPLIT_UP2  4194304.0f       // 2^22
#define SPLIT_DN   4.8828125e-4f    // 2^-11

// ---------------- static scratch ----------------
__device__ __half g_Tw[4][W_ELEMS];
__device__ __half g_X1[BT * D_MODEL], g_X2[BT * D_MODEL], g_X3[BT * D_MODEL];
__device__ __half g_Q1[BT * D_MODEL], g_Q2[BT * D_MODEL], g_Q3[BT * D_MODEL];
__device__ __half g_K1[BT * D_MODEL], g_K2[BT * D_MODEL], g_K3[BT * D_MODEL];
__device__ float  g_V[BT * D_MODEL];
__device__ __half g_O1[BT * D_MODEL], g_O2[BT * D_MODEL], g_O3[BT * D_MODEL];
__device__ float  g_Y[BT * D_MODEL];
__device__ float  g_S[(size_t)BATCH * N_HEADS * T_LEN * T_LEN];   // 512 MB
__device__ unsigned g_rmax[BATCH * N_HEADS * T_LEN];
__device__ double g_red[4][1024], g_red2a[4][1024], g_red2b[4][1024];
__device__ float  g_delta[4], g_alphaf[4], g_maxp[4096], g_scale;

// ---------------- helpers ----------------
__device__ __forceinline__ uint32_t smem_u32(const void* p) {
    uint32_t a;
    asm("{ .reg .u64 t; cvta.to.shared.u64 t, %1; cvt.u32.u64 %0, t; }" : "=r"(a) : "l"(p));
    return a;
}
__device__ __forceinline__ void ldsm4(uint32_t (&r)[4], uint32_t addr) {
    asm volatile("ldmatrix.sync.aligned.m8n8.x4.shared.b16 {%0,%1,%2,%3}, [%4];"
                 : "=r"(r[0]), "=r"(r[1]), "=r"(r[2]), "=r"(r[3]) : "r"(addr));
}
__device__ __forceinline__ void mma16816(float (&d)[4], const uint32_t (&a)[4],
                                         uint32_t b0, uint32_t b1) {
    asm volatile("mma.sync.aligned.m16n8k16.row.col.f32.f16.f16.f32 "
                 "{%0,%1,%2,%3}, {%4,%5,%6,%7}, {%8,%9}, {%0,%1,%2,%3};"
                 : "+f"(d[0]), "+f"(d[1]), "+f"(d[2]), "+f"(d[3])
                 : "r"(a[0]), "r"(a[1]), "r"(a[2]), "r"(a[3]), "r"(b0), "r"(b1));
}
__device__ __forceinline__ unsigned fenc(float f) {
    unsigned b = __float_as_uint(f);
    return (b & 0x80000000u) ? ~b : (b | 0x80000000u);
}
__device__ __forceinline__ float fdec(unsigned u) {
    unsigned b = (u & 0x80000000u) ? (u & 0x7FFFFFFFu) : ~u;
    return __uint_as_float(b);
}
// scaled 3-way split: y = p1 + 2^-11*p2s + 2^-22*p3s, all parts normal-range
__device__ __forceinline__ void split3s(float y, __half& p1, __half& p2, __half& p3) {
    p1 = __float2half_rn(y);
    float r = y - __half2float(p1);
    p2 = __float2half_rn(r * SPLIT_UP);
    float r2 = r - __half2float(p2) * SPLIT_DN;
    p3 = __float2half_rn(r2 * SPLIT_UP2);
}
__device__ __forceinline__ uint32_t packh2(__half a, __half b) {
    __half2 h = __halves2half2(a, b);
    return *(uint32_t*)&h;
}

// ---------------- weight stats (exact doubles) ----------------
__device__ __forceinline__ const float* pick_w(const float* W0, const float* W1,
                                               const float* W2, const float* W3, int y) {
    return y == 0 ? W0 : (y == 1 ? W1 : (y == 2 ? W2 : W3));
}
__global__ void k_rmax_init() { g_rmax[blockIdx.x * 1024 + threadIdx.x] = 0u; }

__global__ void k_wabs(const float* __restrict__ W0, const float* __restrict__ W1,
                       const float* __restrict__ W2, const float* __restrict__ W3) {
    const float* W = pick_w(W0, W1, W2, W3, blockIdx.y);
    __shared__ double sm[256];
    int base = blockIdx.x * 1024;
    double s = 0.0;
    for (int i = threadIdx.x; i < 1024; i += 256) s += (double)fabsf(W[base + i]);
    sm[threadIdx.x] = s; __syncthreads();
    for (int st = 128; st > 0; st >>= 1) {
        if (threadIdx.x < st) sm[threadIdx.x] += sm[threadIdx.x + st];
        __syncthreads();
    }
    if (threadIdx.x == 0) g_red[blockIdx.y][blockIdx.x] = sm[0];
}
__global__ void k_wmask(const float* __restrict__ W0, const float* __restrict__ W1,
                        const float* __restrict__ W2, const float* __restrict__ W3) {
    int y = blockIdx.y;
    const float* W = pick_w(W0, W1, W2, W3, y);
    __shared__ double sa[256], sb[256];
    double s = 0.0;
    for (int i = threadIdx.x; i < 1024; i += 256) s += g_red[y][i];
    sa[threadIdx.x] = s; __syncthreads();
    for (int st = 128; st > 0; st >>= 1) {
        if (threadIdx.x < st) sa[threadIdx.x] += sa[threadIdx.x + st];
        __syncthreads();
    }
    float delta = (float)(0.05 * (sa[0] / (double)W_ELEMS));
    if (blockIdx.x == 0 && threadIdx.x == 0) g_delta[y] = delta;
    __syncthreads();
    int base = blockIdx.x * 1024;
    double s1 = 0.0, s2 = 0.0;
    for (int i = threadIdx.x; i < 1024; i += 256) {
        float a = fabsf(W[base + i]);
        if (a > delta) { s1 += (double)a; s2 += 1.0; }
    }
    sa[threadIdx.x] = s1; sb[threadIdx.x] = s2; __syncthreads();
    for (int st = 128; st > 0; st >>= 1) {
        if (threadIdx.x < st) { sa[threadIdx.x] += sa[threadIdx.x + st]; sb[threadIdx.x] += sb[threadIdx.x + st]; }
        __syncthreads();
    }
    if (threadIdx.x == 0) { g_red2a[y][blockIdx.x] = sa[0]; g_red2b[y][blockIdx.x] = sb[0]; }
}
__global__ void k_wtern(const float* __restrict__ W0, const float* __restrict__ W1,
                        const float* __restrict__ W2, const float* __restrict__ W3) {
    int y = blockIdx.y;
    const float* W = pick_w(W0, W1, W2, W3, y);
    __shared__ double sa[1024], sb[1024];
    sa[threadIdx.x] = g_red2a[y][threadIdx.x];
    sb[threadIdx.x] = g_red2b[y][threadIdx.x];
    __syncthreads();
    for (int st = 512; st > 0; st >>= 1) {
        if (threadIdx.x < st) { sa[threadIdx.x] += sa[threadIdx.x + st]; sb[threadIdx.x] += sb[threadIdx.x + st]; }
        __syncthreads();
    }
    float alpha = (float)(sa[0] / fmax(sb[0], 1.0));
    if (blockIdx.x == 0 && threadIdx.x == 0) g_alphaf[y] = alpha;
    float delta = g_delta[y];
    int i = blockIdx.x * 1024 + threadIdx.x;
    float w = W[i];
    float t = (fabsf(w) > delta) ? ((w > 0.0f) ? 1.0f : -1.0f) : 0.0f;
    g_Tw[y][i] = __float2half_rn(t);
}

__global__ void k_split3(const float* __restrict__ X) {
    int i = blockIdx.x * 1024 + threadIdx.x;
    __half p1, p2, p3;
    split3s(X[i], p1, p2, p3);
    g_X1[i] = p1; g_X2[i] = p2; g_X3[i] = p3;
}

// ---------------- 128x64-half tile loader, chunk-xor swizzle ----------------
__device__ __forceinline__ void load_tile_h(__half* s, const __half* __restrict__ g,
                                            int row0, int col0) {
    int tid = threadIdx.x;
#pragma unroll
    for (int i = 0; i < 4; i++) {
        int idx = tid + i * 256;
        int row = idx >> 3, c = idx & 7;
        uint4 v = *(const uint4*)(g + (size_t)(row0 + row) * D_MODEL + col0 + c * 8);
        int cs = c ^ (row & 7);
        *(uint4*)((char*)s + row * 128 + cs * 16) = v;
    }
}

// one BK=64 stage of 128x128 HMMA; warp (wm,wn) owns 64x32
__device__ __forceinline__ void hgemm_core(uint32_t aB, uint32_t bB, int wm, int wn,
                                           int lane, float (&acc)[4][4][4]) {
#pragma unroll
    for (int kf = 0; kf < 4; kf++) {
        uint32_t a[4][4];
#pragma unroll
        for (int i = 0; i < 4; i++) {
            int row = wm * 64 + i * 16 + (lane & 15);
            int ch = (kf * 2 + (lane >> 4)) ^ (row & 7);
            ldsm4(a[i], aB + (uint32_t)(row * 8 + ch) * 16);
        }
        uint32_t b[4][2];
#pragma unroll
        for (int jp = 0; jp < 2; jp++) {
            int nrow = wn * 32 + jp * 16 + (lane & 7) + ((lane >> 4) << 3);
            int ch = (kf * 2 + ((lane >> 3) & 1)) ^ (nrow & 7);
            uint32_t t[4];
            ldsm4(t, bB + (uint32_t)(nrow * 8 + ch) * 16);
            b[jp * 2][0] = t[0]; b[jp * 2][1] = t[1];
            b[jp * 2 + 1][0] = t[2]; b[jp * 2 + 1][1] = t[3];
        }
#pragma unroll
        for (int i = 0; i < 4; i++)
#pragma unroll
            for (int j = 0; j < 4; j++)
                mma16816(acc[i][j], a[i], b[j][0], b[j][1]);
    }
}
__device__ __forceinline__ void acc_scale(float (&acc)[4][4][4], float s) {
#pragma unroll
    for (int i = 0; i < 4; i++)
#pragma unroll
        for (int j = 0; j < 4; j++)
#pragma unroll
            for (int q = 0; q < 4; q++) acc[i][j][q] *= s;
}

// ---------------- projection GEMM: C = (p1 + 2^-11 p2 + 2^-22 p3) @ Tw^T * alpha + bias ----
__global__ void __launch_bounds__(256)
k_hproj(const __half* __restrict__ A0, const __half* __restrict__ A1,
        const __half* __restrict__ A2, const __half* __restrict__ Bw, int widx,
        const float* __restrict__ bias, float* __restrict__ outF,
        __half* __restrict__ O1, __half* __restrict__ O2, __half* __restrict__ O3,
        int mode) {
    extern __shared__ __align__(16) __half smp[];
    __half* sA = smp;
    __half* sB = smp + 8192;

    int tid = threadIdx.x, lane = tid & 31, w = tid >> 5, wm = w >> 2, wn = w & 3;
    int m0 = blockIdx.x * 128, n0 = blockIdx.y * 128;
    float acc[4][4][4];
#pragma unroll
    for (int i = 0; i < 4; i++)
#pragma unroll
        for (int j = 0; j < 4; j++)
#pragma unroll
            for (int q = 0; q < 4; q++) acc[i][j][q] = 0.0f;
    uint32_t aB = smem_u32(sA), bB = smem_u32(sB);

    for (int sp = 0; sp < 3; sp++) {
        const __half* A = (sp == 0) ? A2 : ((sp == 1) ? A1 : A0);   // smallest scale first
        for (int kt = 0; kt < 16; kt++) {
            __syncthreads();
            load_tile_h(sA, A, m0, kt * 64);
            load_tile_h(sB, Bw, n0, kt * 64);
            __syncthreads();
            hgemm_core(aB, bB, wm, wn, lane, acc);
        }
        if (sp < 2) acc_scale(acc, SPLIT_DN);
    }

    float alpha = g_alphaf[widx];
    int gid = lane >> 2, tid2 = lane & 3;
#pragma unroll
    for (int i = 0; i < 4; i++) {
#pragma unroll
        for (int j = 0; j < 4; j++) {
            int row = m0 + wm * 64 + i * 16 + gid;
            int col = n0 + wn * 32 + j * 8 + tid2 * 2;
            float b0 = bias[col], b1 = bias[col + 1];
            float y00 = acc[i][j][0] * alpha + b0, y01 = acc[i][j][1] * alpha + b1;
            float y10 = acc[i][j][2] * alpha + b0, y11 = acc[i][j][3] * alpha + b1;
            if (mode == 0) {
                *(float2*)(outF + (size_t)row * D_MODEL + col) = make_float2(y00, y01);
                *(float2*)(outF + (size_t)(row + 8) * D_MODEL + col) = make_float2(y10, y11);
            } else {
                __half u1, u2, u3, v1, v2, v3;
                size_t r0 = (size_t)row * D_MODEL + col;
                size_t r1 = (size_t)(row + 8) * D_MODEL + col;
                split3s(y00, u1, u2, u3); split3s(y01, v1, v2, v3);
                *(uint32_t*)(O1 + r0) = packh2(u1, v1);
                *(uint32_t*)(O2 + r0) = packh2(u2, v2);
                *(uint32_t*)(O3 + r0) = packh2(u3, v3);
                split3s(y10, u1, u2, u3); split3s(y11, v1, v2, v3);
                *(uint32_t*)(O1 + r1) = packh2(u1, v1);
                *(uint32_t*)(O2 + r1) = packh2(u2, v2);
                *(uint32_t*)(O3 + r1) = packh2(u3, v3);
            }
        }
    }
}

// ---------------- S = (QK^T)/8 via grouped scaled cross-terms + row max ----------------
__global__ void __launch_bounds__(256)
k_hs() {
    extern __shared__ __align__(16) __half sms[];
    __half* sQ[3] = {sms, sms + 8192, sms + 16384};
    __half* sK[3] = {sms + 24576, sms + 32768, sms + 40960};

    int tid = threadIdx.x, lane = tid & 31, w = tid >> 5, wm = w >> 2, wn = w & 3;
    int z = blockIdx.z, b = z >> 4, h = z & 15;
    int arow0 = b * T_LEN + blockIdx.x * 128;
    int brow0 = b * T_LEN + blockIdx.y * 128;
    int col0 = h * 64;
    float acc[4][4][4];
#pragma unroll
    for (int i = 0; i < 4; i++)
#pragma unroll
        for (int j = 0; j < 4; j++)
#pragma unroll
            for (int q = 0; q < 4; q++) acc[i][j][q] = 0.0f;

    load_tile_h(sQ[0], g_Q1, arow0, col0);
    load_tile_h(sQ[1], g_Q2, arow0, col0);
    load_tile_h(sQ[2], g_Q3, arow0, col0);
    load_tile_h(sK[0], g_K1, brow0, col0);
    load_tile_h(sK[1], g_K2, brow0, col0);
    load_tile_h(sK[2], g_K3, brow0, col0);
    __syncthreads();

    uint32_t qB[3] = {smem_u32(sQ[0]), smem_u32(sQ[1]), smem_u32(sQ[2])};
    uint32_t kB[3] = {smem_u32(sK[0]), smem_u32(sK[1]), smem_u32(sK[2])};
    // Horner over scale groups: G2 (2^-22), G1 (2^-11), G0 (1)
    hgemm_core(qB[1], kB[1], wm, wn, lane, acc);   // p2*k2
    hgemm_core(qB[0], kB[2], wm, wn, lane, acc);   // p1*k3
    hgemm_core(qB[2], kB[0], wm, wn, lane, acc);   // p3*k1
    acc_scale(acc, SPLIT_DN);
    hgemm_core(qB[0], kB[1], wm, wn, lane, acc);   // p1*k2
    hgemm_core(qB[1], kB[0], wm, wn, lane, acc);   // p2*k1
    acc_scale(acc, SPLIT_DN);
    hgemm_core(qB[0], kB[0], wm, wn, lane, acc);   // p1*k1

    int gid = lane >> 2, tid2 = lane & 3;
    size_t zrow = (size_t)z * T_LEN;
#pragma unroll
    for (int i = 0; i < 4; i++) {
        int rl0 = blockIdx.x * 128 + wm * 64 + i * 16 + gid;
        float m0v = -INFINITY, m1v = -INFINITY;
#pragma unroll
        for (int j = 0; j < 4; j++) {
            int col = blockIdx.y * 128 + wn * 32 + j * 8 + tid2 * 2;
            float y00 = acc[i][j][0] * 0.125f, y01 = acc[i][j][1] * 0.125f;
            float y10 = acc[i][j][2] * 0.125f, y11 = acc[i][j][3] * 0.125f;
            *(float2*)(g_S + (zrow + rl0) * T_LEN + col) = make_float2(y00, y01);
            *(float2*)(g_S + (zrow + rl0 + 8) * T_LEN + col) = make_float2(y10, y11);
            m0v = fmaxf(m0v, fmaxf(y00, y01));
            m1v = fmaxf(m1v, fmaxf(y10, y11));
        }
        atomicMax(&g_rmax[zrow + rl0], fenc(m0v));
        atomicMax(&g_rmax[zrow + rl0 + 8], fenc(m1v));
    }
}

// ---- fused softmax + PV (SIMT fp32, two-level Kahan for BOTH rsum and acc) ----
__global__ void __launch_bounds__(256)
k_pv() {
    __shared__ float As[16][132];
    __shared__ float Bs[16][68];
    __shared__ float m_s[128];

    int tid = threadIdx.x, ty = tid >> 4, tx = tid & 15;
    int z = blockIdx.y, b = z >> 4, h = z & 15;
    int rowBase = blockIdx.x * 128;
    const float* Sp = g_S + ((size_t)z * T_LEN + rowBase) * T_LEN;
    const float* Vp = g_V + (size_t)b * T_LEN * D_MODEL + h * 64;

    if (tid < 128) m_s[tid] = fdec(g_rmax[(size_t)z * T_LEN + rowBase + tid]);
    __syncthreads();

    float acc[8][4], compA[8][4], rsum[8], compR[8];
#pragma unroll
    for (int i = 0; i < 8; i++) {
        rsum[i] = 0.0f; compR[i] = 0.0f;
#pragma unroll
        for (int j = 0; j < 4; j++) { acc[i][j] = 0.0f; compA[i][j] = 0.0f; }
    }

    for (int k0 = 0; k0 < T_LEN; k0 += 16) {
#pragma unroll
        for (int i = 0; i < 2; i++) {
            int idx = tid + i * 256;
            int row = idx >> 2, kq = idx & 3;
            float4 v = *(const float4*)(Sp + (size_t)row * T_LEN + k0 + kq * 4);
            float m = m_s[row];
            As[kq * 4 + 0][row] = expf(v.x - m);
            As[kq * 4 + 1][row] = expf(v.y - m);
            As[kq * 4 + 2][row] = expf(v.z - m);
            As[kq * 4 + 3][row] = expf(v.w - m);
        }
        {
            int kr = tid >> 4, n4 = tid & 15;
            *(float4*)&Bs[kr][n4 * 4] = *(const float4*)(Vp + (size_t)(k0 + kr) * D_MODEL + n4 * 4);
        }
        __syncthreads();
        float cacc[8][4], csum[8];
#pragma unroll
        for (int i = 0; i < 8; i++) {
            csum[i] = 0.0f;
#pragma unroll
            for (int j = 0; j < 4; j++) cacc[i][j] = 0.0f;
        }
#pragma unroll
        for (int kk = 0; kk < 16; kk++) {
            float4 a0 = *(float4*)&As[kk][ty * 4];
            float4 a1 = *(float4*)&As[kk][64 + ty * 4];
            float4 bv = *(float4*)&Bs[kk][tx * 4];
            float ar[8] = {a0.x, a0.y, a0.z, a0.w, a1.x, a1.y, a1.z, a1.w};
            float br[4] = {bv.x, bv.y, bv.z, bv.w};
#pragma unroll
            for (int i = 0; i < 8; i++) {
                csum[i] += ar[i];
#pragma unroll
                for (int j = 0; j < 4; j++)
                    cacc[i][j] = fmaf(ar[i], br[j], cacc[i][j]);
            }
        }
        // Kahan merge chunk sums into running totals (kills sequential random walk)
#pragma unroll
        for (int i = 0; i < 8; i++) {
            float yv = csum[i] - compR[i];
            float t = rsum[i] + yv;
            compR[i] = (t - rsum[i]) - yv;
            rsum[i] = t;
#pragma unroll
            for (int j = 0; j < 4; j++) {
                float ya = cacc[i][j] - compA[i][j];
                float ta = acc[i][j] + ya;
                compA[i][j] = (ta - acc[i][j]) - ya;
                acc[i][j] = ta;
            }
        }
        __syncthreads();
    }

#pragma unroll
    for (int i = 0; i < 8; i++) {
        int lr = (i < 4) ? (ty * 4 + i) : (64 + ty * 4 + i - 4);
        size_t orow = (size_t)(b * T_LEN + rowBase + lr) * D_MODEL + h * 64 + tx * 4;
        __half p1[4], p2[4], p3[4];
#pragma unroll
        for (int j = 0; j < 4; j++) split3s(acc[i][j] / rsum[i], p1[j], p2[j], p3[j]);
        *(uint2*)(g_O1 + orow) = make_uint2(packh2(p1[0], p1[1]), packh2(p1[2], p1[3]));
        *(uint2*)(g_O2 + orow) = make_uint2(packh2(p2[0], p2[1]), packh2(p2[2], p2[3]));
        *(uint2*)(g_O3 + orow) = make_uint2(packh2(p3[0], p3[1]), packh2(p3[2], p3[3]));
    }
}

// ---------------- fp4 quant ----------------
__global__ void k_absmax_partial(const float* __restrict__ Y) {
    __shared__ float sm[256];
    int base = blockIdx.x * 1024, tid = threadIdx.x;
    float m = 0.0f;
#pragma unroll
    for (int i = 0; i < 4; i++) m = fmaxf(m, fabsf(Y[base + tid + i * 256]));
    sm[tid] = m; __syncthreads();
    for (int st = 128; st > 0; st >>= 1) {
        if (tid < st) sm[tid] = fmaxf(sm[tid], sm[tid + st]);
        __syncthreads();
    }
    if (tid == 0) g_maxp[blockIdx.x] = sm[0];
}
__global__ void k_absmax_final() {
    __shared__ float sm[1024];
    int tid = threadIdx.x;
    float m = 0.0f;
#pragma unroll
    for (int i = 0; i < 4; i++) m = fmaxf(m, g_maxp[tid + i * 1024]);
    sm[tid] = m; __syncthreads();
    for (int st = 512; st > 0; st >>= 1) {
        if (tid < st) sm[tid] = fmaxf(sm[tid], sm[tid + st]);
        __syncthreads();
    }
    if (tid == 0) g_scale = fmaxf(sm[0] / 7.0f, 1e-8f);
}
__global__ void k_quant(const float* __restrict__ Y, float* __restrict__ out) {
    int i = blockIdx.x * 1024 + threadIdx.x;
    float s = g_scale;
    float q = rintf(Y[i] / s);
    out[i] = fminf(7.0f, fmaxf(-7.0f, q)) * s;
}

// ---------------- launch ----------------
extern "C" void kernel_launch(void* const* d_in, const int* in_sizes, int n_in,
                              void* d_out, int out_size) {
    const float* x  = (const float*)d_in[0];
    const float* Wq = (const float*)d_in[1];
    const float* bq = (const float*)d_in[2];
    const float* Wk = (const float*)d_in[3];
    const float* bk = (const float*)d_in[4];
    const float* Wv = (const float*)d_in[5];
    const float* bv = (const float*)d_in[6];
    const float* Wo = (const float*)d_in[7];
    const float* bo = (const float*)d_in[8];
    float* out = (float*)d_out;

    __half *tw, *x1, *x2, *x3, *q1, *q2, *q3, *kk1, *kk2, *kk3, *o1, *o2, *o3;
    float *v, *y;
    cudaGetSymbolAddress((void**)&tw, g_Tw);
    cudaGetSymbolAddress((void**)&x1, g_X1);  cudaGetSymbolAddress((void**)&x2, g_X2);
    cudaGetSymbolAddress((void**)&x3, g_X3);
    cudaGetSymbolAddress((void**)&q1, g_Q1);  cudaGetSymbolAddress((void**)&q2, g_Q2);
    cudaGetSymbolAddress((void**)&q3, g_Q3);
    cudaGetSymbolAddress((void**)&kk1, g_K1); cudaGetSymbolAddress((void**)&kk2, g_K2);
    cudaGetSymbolAddress((void**)&kk3, g_K3);
    cudaGetSymbolAddress((void**)&o1, g_O1);  cudaGetSymbolAddress((void**)&o2, g_O2);
    cudaGetSymbolAddress((void**)&o3, g_O3);
    cudaGetSymbolAddress((void**)&v, g_V);    cudaGetSymbolAddress((void**)&y, g_Y);

    cudaFuncSetAttribute(k_hproj, cudaFuncAttributeMaxDynamicSharedMemorySize, 32768);
    cudaFuncSetAttribute(k_hs, cudaFuncAttributeMaxDynamicSharedMemorySize, 98304);

    // 0-3) init + weight stats + ternarize
    k_rmax_init<<<64, 1024>>>();
    k_wabs<<<dim3(1024, 4), 256>>>(Wq, Wk, Wv, Wo);
    k_wmask<<<dim3(1024, 4), 256>>>(Wq, Wk, Wv, Wo);
    k_wtern<<<dim3(1024, 4), 1024>>>(Wq, Wk, Wv, Wo);

    // 4) x -> scaled fp16 triple
    k_split3<<<4096, 1024>>>(x);

    // 5-7) projections (HMMA, scaled 3-split): Q,K -> fp16 triples; V -> fp32
    k_hproj<<<dim3(32, 8), 256, 32768>>>(x1, x2, x3, tw + 0 * (size_t)W_ELEMS, 0, bq,
                                         nullptr, q1, q2, q3, 1);
    k_hproj<<<dim3(32, 8), 256, 32768>>>(x1, x2, x3, tw + 1 * (size_t)W_ELEMS, 1, bk,
                                         nullptr, kk1, kk2, kk3, 1);
    k_hproj<<<dim3(32, 8), 256, 32768>>>(x1, x2, x3, tw + 2 * (size_t)W_ELEMS, 2, bv,
                                         v, nullptr, nullptr, nullptr, 0);

    // 8) S = QK^T/8 (grouped scaled cross-terms) + row max
    k_hs<<<dim3(16, 16, BATCH * N_HEADS), 256, 98304>>>();

    // 9) fused softmax + PV (two-level Kahan acc + rsum) -> scaled fp16 triples
    k_pv<<<dim3(16, BATCH * N_HEADS), 256>>>();

    // 10) out projection -> Y fp32
    k_hproj<<<dim3(32, 8), 256, 32768>>>(o1, o2, o3, tw + 3 * (size_t)W_ELEMS, 3, bo,
                                         y, nullptr, nullptr, nullptr, 0);

    // 11-13) fp4 quant
    k_absmax_partial<<<4096, 256>>>(y);
    k_absmax_final<<<1, 1024>>>();
    k_quant<<<4096, 1024>>>(y, out);
}

// round 9
// speedup vs baseline: 1.4262x; 1.2093x over previous
#include <cuda_runtime.h>
#include <cuda_fp16.h>
#include <math.h>
#include <stdint.h>

#define D_MODEL 1024
#define T_LEN   2048
#define BATCH   2
#define N_HEADS 16
#define D_HEAD  64
#define BT      (BATCH * T_LEN)
#define W_ELEMS (D_MODEL * D_MODEL)

#define SPLIT_UP   2048.0f          // 2^11
#define SPLIT_UP2  4194304.0f       // 2^22
#define SPLIT_DN   4.8828125e-4f    // 2^-11

// ---------------- static scratch ----------------
__device__ __half g_Tw[4][W_ELEMS];
__device__ __half g_X1[BT * D_MODEL], g_X2[BT * D_MODEL], g_X3[BT * D_MODEL];
__device__ __half g_Q1[BT * D_MODEL], g_Q2[BT * D_MODEL], g_Q3[BT * D_MODEL];
__device__ __half g_K1[BT * D_MODEL], g_K2[BT * D_MODEL], g_K3[BT * D_MODEL];
__device__ float  g_V[BT * D_MODEL];
__device__ __half g_O1[BT * D_MODEL], g_O2[BT * D_MODEL], g_O3[BT * D_MODEL];
__device__ float  g_Y[BT * D_MODEL];
__device__ float  g_S[(size_t)BATCH * N_HEADS * T_LEN * T_LEN];   // 512 MB
__device__ unsigned g_rmax[BATCH * N_HEADS * T_LEN];
__device__ double g_red[4][1024], g_red2a[4][1024], g_red2b[4][1024];
__device__ float  g_delta[4], g_alphaf[4], g_maxp[4096], g_scale;

// ---------------- helpers ----------------
__device__ __forceinline__ uint32_t smem_u32(const void* p) {
    uint32_t a;
    asm("{ .reg .u64 t; cvta.to.shared.u64 t, %1; cvt.u32.u64 %0, t; }" : "=r"(a) : "l"(p));
    return a;
}
__device__ __forceinline__ void ldsm4(uint32_t (&r)[4], uint32_t addr) {
    asm volatile("ldmatrix.sync.aligned.m8n8.x4.shared.b16 {%0,%1,%2,%3}, [%4];"
                 : "=r"(r[0]), "=r"(r[1]), "=r"(r[2]), "=r"(r[3]) : "r"(addr));
}
__device__ __forceinline__ void mma16816(float (&d)[4], const uint32_t (&a)[4],
                                         uint32_t b0, uint32_t b1) {
    asm volatile("mma.sync.aligned.m16n8k16.row.col.f32.f16.f16.f32 "
                 "{%0,%1,%2,%3}, {%4,%5,%6,%7}, {%8,%9}, {%0,%1,%2,%3};"
                 : "+f"(d[0]), "+f"(d[1]), "+f"(d[2]), "+f"(d[3])
                 : "r"(a[0]), "r"(a[1]), "r"(a[2]), "r"(a[3]), "r"(b0), "r"(b1));
}
__device__ __forceinline__ unsigned fenc(float f) {
    unsigned b = __float_as_uint(f);
    return (b & 0x80000000u) ? ~b : (b | 0x80000000u);
}
__device__ __forceinline__ float fdec(unsigned u) {
    unsigned b = (u & 0x80000000u) ? (u & 0x7FFFFFFFu) : ~u;
    return __uint_as_float(b);
}
// scaled 3-way split: y = p1 + 2^-11*p2s + 2^-22*p3s, all parts normal-range
__device__ __forceinline__ void split3s(float y, __half& p1, __half& p2, __half& p3) {
    p1 = __float2half_rn(y);
    float r = y - __half2float(p1);
    p2 = __float2half_rn(r * SPLIT_UP);
    float r2 = r - __half2float(p2) * SPLIT_DN;
    p3 = __float2half_rn(r2 * SPLIT_UP2);
}
__device__ __forceinline__ uint32_t packh2(__half a, __half b) {
    __half2 h = __halves2half2(a, b);
    return *(uint32_t*)&h;
}

// ---------------- weight stats (exact doubles) ----------------
__device__ __forceinline__ const float* pick_w(const float* W0, const float* W1,
                                               const float* W2, const float* W3, int y) {
    return y == 0 ? W0 : (y == 1 ? W1 : (y == 2 ? W2 : W3));
}
__global__ void k_rmax_init() { g_rmax[blockIdx.x * 1024 + threadIdx.x] = 0u; }

__global__ void k_wabs(const float* __restrict__ W0, const float* __restrict__ W1,
                       const float* __restrict__ W2, const float* __restrict__ W3) {
    const float* W = pick_w(W0, W1, W2, W3, blockIdx.y);
    __shared__ double sm[256];
    int base = blockIdx.x * 1024;
    double s = 0.0;
    for (int i = threadIdx.x; i < 1024; i += 256) s += (double)fabsf(W[base + i]);
    sm[threadIdx.x] = s; __syncthreads();
    for (int st = 128; st > 0; st >>= 1) {
        if (threadIdx.x < st) sm[threadIdx.x] += sm[threadIdx.x + st];
        __syncthreads();
    }
    if (threadIdx.x == 0) g_red[blockIdx.y][blockIdx.x] = sm[0];
}
__global__ void k_wmask(const float* __restrict__ W0, const float* __restrict__ W1,
                        const float* __restrict__ W2, const float* __restrict__ W3) {
    int y = blockIdx.y;
    const float* W = pick_w(W0, W1, W2, W3, y);
    __shared__ double sa[256], sb[256];
    double s = 0.0;
    for (int i = threadIdx.x; i < 1024; i += 256) s += g_red[y][i];
    sa[threadIdx.x] = s; __syncthreads();
    for (int st = 128; st > 0; st >>= 1) {
        if (threadIdx.x < st) sa[threadIdx.x] += sa[threadIdx.x + st];
        __syncthreads();
    }
    float delta = (float)(0.05 * (sa[0] / (double)W_ELEMS));
    if (blockIdx.x == 0 && threadIdx.x == 0) g_delta[y] = delta;
    __syncthreads();
    int base = blockIdx.x * 1024;
    double s1 = 0.0, s2 = 0.0;
    for (int i = threadIdx.x; i < 1024; i += 256) {
        float a = fabsf(W[base + i]);
        if (a > delta) { s1 += (double)a; s2 += 1.0; }
    }
    sa[threadIdx.x] = s1; sb[threadIdx.x] = s2; __syncthreads();
    for (int st = 128; st > 0; st >>= 1) {
        if (threadIdx.x < st) { sa[threadIdx.x] += sa[threadIdx.x + st]; sb[threadIdx.x] += sb[threadIdx.x + st]; }
        __syncthreads();
    }
    if (threadIdx.x == 0) { g_red2a[y][blockIdx.x] = sa[0]; g_red2b[y][blockIdx.x] = sb[0]; }
}
// alpha finalize: 4 blocks only — identical reduction arithmetic to R8's k_wtern
__global__ void k_walpha() {
    int y = blockIdx.x;
    __shared__ double sa[1024], sb[1024];
    sa[threadIdx.x] = g_red2a[y][threadIdx.x];
    sb[threadIdx.x] = g_red2b[y][threadIdx.x];
    __syncthreads();
    for (int st = 512; st > 0; st >>= 1) {
        if (threadIdx.x < st) { sa[threadIdx.x] += sa[threadIdx.x + st]; sb[threadIdx.x] += sb[threadIdx.x + st]; }
        __syncthreads();
    }
    if (threadIdx.x == 0) g_alphaf[y] = (float)(sa[0] / fmax(sb[0], 1.0));
}
// pure elementwise ternarize (no per-block reduction)
__global__ void k_wtern(const float* __restrict__ W0, const float* __restrict__ W1,
                        const float* __restrict__ W2, const float* __restrict__ W3) {
    int y = blockIdx.y;
    const float* W = pick_w(W0, W1, W2, W3, y);
    float delta = g_delta[y];
    int i = blockIdx.x * 1024 + threadIdx.x;
    float w = W[i];
    float t = (fabsf(w) > delta) ? ((w > 0.0f) ? 1.0f : -1.0f) : 0.0f;
    g_Tw[y][i] = __float2half_rn(t);
}

__global__ void k_split3(const float* __restrict__ X) {
    int i = blockIdx.x * 1024 + threadIdx.x;
    __half p1, p2, p3;
    split3s(X[i], p1, p2, p3);
    g_X1[i] = p1; g_X2[i] = p2; g_X3[i] = p3;
}

// ---------------- tile staging: LDG into regs, STS with chunk-xor swizzle ----------------
struct TileRegs { uint4 v[4]; };
__device__ __forceinline__ void tile_ldg(TileRegs& r, const __half* __restrict__ g,
                                         int row0, int col0) {
    int tid = threadIdx.x;
#pragma unroll
    for (int i = 0; i < 4; i++) {
        int idx = tid + i * 256;
        int row = idx >> 3, c = idx & 7;
        r.v[i] = *(const uint4*)(g + (size_t)(row0 + row) * D_MODEL + col0 + c * 8);
    }
}
__device__ __forceinline__ void tile_sts(__half* s, const TileRegs& r) {
    int tid = threadIdx.x;
#pragma unroll
    for (int i = 0; i < 4; i++) {
        int idx = tid + i * 256;
        int row = idx >> 3, c = idx & 7;
        int cs = c ^ (row & 7);
        *(uint4*)((char*)s + row * 128 + cs * 16) = r.v[i];
    }
}
__device__ __forceinline__ void load_tile_h(__half* s, const __half* __restrict__ g,
                                            int row0, int col0) {
    TileRegs r;
    tile_ldg(r, g, row0, col0);
    tile_sts(s, r);
}

// one BK=64 stage of 128x128 HMMA; warp (wm,wn) owns 64x32
__device__ __forceinline__ void hgemm_core(uint32_t aB, uint32_t bB, int wm, int wn,
                                           int lane, float (&acc)[4][4][4]) {
#pragma unroll
    for (int kf = 0; kf < 4; kf++) {
        uint32_t a[4][4];
#pragma unroll
        for (int i = 0; i < 4; i++) {
            int row = wm * 64 + i * 16 + (lane & 15);
            int ch = (kf * 2 + (lane >> 4)) ^ (row & 7);
            ldsm4(a[i], aB + (uint32_t)(row * 8 + ch) * 16);
        }
        uint32_t b[4][2];
#pragma unroll
        for (int jp = 0; jp < 2; jp++) {
            int nrow = wn * 32 + jp * 16 + (lane & 7) + ((lane >> 4) << 3);
            int ch = (kf * 2 + ((lane >> 3) & 1)) ^ (nrow & 7);
            uint32_t t[4];
            ldsm4(t, bB + (uint32_t)(nrow * 8 + ch) * 16);
            b[jp * 2][0] = t[0]; b[jp * 2][1] = t[1];
            b[jp * 2 + 1][0] = t[2]; b[jp * 2 + 1][1] = t[3];
        }
#pragma unroll
        for (int i = 0; i < 4; i++)
#pragma unroll
            for (int j = 0; j < 4; j++)
                mma16816(acc[i][j], a[i], b[j][0], b[j][1]);
    }
}
__device__ __forceinline__ void acc_scale(float (&acc)[4][4][4], float s) {
#pragma unroll
    for (int i = 0; i < 4; i++)
#pragma unroll
        for (int j = 0; j < 4; j++)
#pragma unroll
            for (int q = 0; q < 4; q++) acc[i][j][q] *= s;
}

// ---------------- projection GEMM with register double-buffering ----------------
__global__ void __launch_bounds__(256)
k_hproj(const __half* __restrict__ A0, const __half* __restrict__ A1,
        const __half* __restrict__ A2, const __half* __restrict__ Bw, int widx,
        const float* __restrict__ bias, float* __restrict__ outF,
        __half* __restrict__ O1, __half* __restrict__ O2, __half* __restrict__ O3,
        int mode) {
    extern __shared__ __align__(16) __half smp[];
    __half* sA = smp;
    __half* sB = smp + 8192;

    int tid = threadIdx.x, lane = tid & 31, w = tid >> 5, wm = w >> 2, wn = w & 3;
    int m0 = blockIdx.x * 128, n0 = blockIdx.y * 128;
    float acc[4][4][4];
#pragma unroll
    for (int i = 0; i < 4; i++)
#pragma unroll
        for (int j = 0; j < 4; j++)
#pragma unroll
            for (int q = 0; q < 4; q++) acc[i][j][q] = 0.0f;
    uint32_t aB = smem_u32(sA), bB = smem_u32(sB);

    const __half* As3[3] = {A2, A1, A0};   // smallest scale first (Horner)
    TileRegs ra, rb;
    tile_ldg(ra, As3[0], m0, 0);
    tile_ldg(rb, Bw, n0, 0);

    for (int st = 0; st < 48; st++) {
        __syncthreads();                // smem free (previous compute done)
        tile_sts(sA, ra);
        tile_sts(sB, rb);
        __syncthreads();
        if (st < 47) {                  // prefetch next stage while computing
            int nst = st + 1;
            tile_ldg(ra, As3[nst >> 4], m0, (nst & 15) * 64);
            tile_ldg(rb, Bw, n0, (nst & 15) * 64);
        }
        hgemm_core(aB, bB, wm, wn, lane, acc);
        if (st == 15 || st == 31) acc_scale(acc, SPLIT_DN);
    }

    float alpha = g_alphaf[widx];
    int gid = lane >> 2, tid2 = lane & 3;
#pragma unroll
    for (int i = 0; i < 4; i++) {
#pragma unroll
        for (int j = 0; j < 4; j++) {
            int row = m0 + wm * 64 + i * 16 + gid;
            int col = n0 + wn * 32 + j * 8 + tid2 * 2;
            float b0 = bias[col], b1 = bias[col + 1];
            float y00 = acc[i][j][0] * alpha + b0, y01 = acc[i][j][1] * alpha + b1;
            float y10 = acc[i][j][2] * alpha + b0, y11 = acc[i][j][3] * alpha + b1;
            if (mode == 0) {
                *(float2*)(outF + (size_t)row * D_MODEL + col) = make_float2(y00, y01);
                *(float2*)(outF + (size_t)(row + 8) * D_MODEL + col) = make_float2(y10, y11);
            } else {
                __half u1, u2, u3, v1, v2, v3;
                size_t r0 = (size_t)row * D_MODEL + col;
                size_t r1 = (size_t)(row + 8) * D_MODEL + col;
                split3s(y00, u1, u2, u3); split3s(y01, v1, v2, v3);
                *(uint32_t*)(O1 + r0) = packh2(u1, v1);
                *(uint32_t*)(O2 + r0) = packh2(u2, v2);
                *(uint32_t*)(O3 + r0) = packh2(u3, v3);
                split3s(y10, u1, u2, u3); split3s(y11, v1, v2, v3);
                *(uint32_t*)(O1 + r1) = packh2(u1, v1);
                *(uint32_t*)(O2 + r1) = packh2(u2, v2);
                *(uint32_t*)(O3 + r1) = packh2(u3, v3);
            }
        }
    }
}

// ---------------- S = (QK^T)/8 via grouped scaled cross-terms + row max ----------------
__global__ void __launch_bounds__(256)
k_hs() {
    extern __shared__ __align__(16) __half sms[];
    __half* sQ[3] = {sms, sms + 8192, sms + 16384};
    __half* sK[3] = {sms + 24576, sms + 32768, sms + 40960};

    int tid = threadIdx.x, lane = tid & 31, w = tid >> 5, wm = w >> 2, wn = w & 3;
    int z = blockIdx.z, b = z >> 4, h = z & 15;
    int arow0 = b * T_LEN + blockIdx.x * 128;
    int brow0 = b * T_LEN + blockIdx.y * 128;
    int col0 = h * 64;
    float acc[4][4][4];
#pragma unroll
    for (int i = 0; i < 4; i++)
#pragma unroll
        for (int j = 0; j < 4; j++)
#pragma unroll
            for (int q = 0; q < 4; q++) acc[i][j][q] = 0.0f;

    load_tile_h(sQ[0], g_Q1, arow0, col0);
    load_tile_h(sQ[1], g_Q2, arow0, col0);
    load_tile_h(sQ[2], g_Q3, arow0, col0);
    load_tile_h(sK[0], g_K1, brow0, col0);
    load_tile_h(sK[1], g_K2, brow0, col0);
    load_tile_h(sK[2], g_K3, brow0, col0);
    __syncthreads();

    uint32_t qB[3] = {smem_u32(sQ[0]), smem_u32(sQ[1]), smem_u32(sQ[2])};
    uint32_t kB[3] = {smem_u32(sK[0]), smem_u32(sK[1]), smem_u32(sK[2])};
    // Horner over scale groups: G2 (2^-22), G1 (2^-11), G0 (1)
    hgemm_core(qB[1], kB[1], wm, wn, lane, acc);   // p2*k2
    hgemm_core(qB[0], kB[2], wm, wn, lane, acc);   // p1*k3
    hgemm_core(qB[2], kB[0], wm, wn, lane, acc);   // p3*k1
    acc_scale(acc, SPLIT_DN);
    hgemm_core(qB[0], kB[1], wm, wn, lane, acc);   // p1*k2
    hgemm_core(qB[1], kB[0], wm, wn, lane, acc);   // p2*k1
    acc_scale(acc, SPLIT_DN);
    hgemm_core(qB[0], kB[0], wm, wn, lane, acc);   // p1*k1

    int gid = lane >> 2, tid2 = lane & 3;
    size_t zrow = (size_t)z * T_LEN;
#pragma unroll
    for (int i = 0; i < 4; i++) {
        int rl0 = blockIdx.x * 128 + wm * 64 + i * 16 + gid;
        float m0v = -INFINITY, m1v = -INFINITY;
#pragma unroll
        for (int j = 0; j < 4; j++) {
            int col = blockIdx.y * 128 + wn * 32 + j * 8 + tid2 * 2;
            float y00 = acc[i][j][0] * 0.125f, y01 = acc[i][j][1] * 0.125f;
            float y10 = acc[i][j][2] * 0.125f, y11 = acc[i][j][3] * 0.125f;
            *(float2*)(g_S + (zrow + rl0) * T_LEN + col) = make_float2(y00, y01);
            *(float2*)(g_S + (zrow + rl0 + 8) * T_LEN + col) = make_float2(y10, y11);
            m0v = fmaxf(m0v, fmaxf(y00, y01));
            m1v = fmaxf(m1v, fmaxf(y10, y11));
        }
        atomicMax(&g_rmax[zrow + rl0], fenc(m0v));
        atomicMax(&g_rmax[zrow + rl0 + 8], fenc(m1v));
    }
}

// ---- fused softmax + PV (SIMT fp32, two-level Kahan; register-staged loads) ----
__global__ void __launch_bounds__(256)
k_pv() {
    __shared__ float As[16][132];
    __shared__ float Bs[16][68];
    __shared__ float m_s[128];

    int tid = threadIdx.x, ty = tid >> 4, tx = tid & 15;
    int z = blockIdx.y, b = z >> 4, h = z & 15;
    int rowBase = blockIdx.x * 128;
    const float* Sp = g_S + ((size_t)z * T_LEN + rowBase) * T_LEN;
    const float* Vp = g_V + (size_t)b * T_LEN * D_MODEL + h * 64;

    if (tid < 128) m_s[tid] = fdec(g_rmax[(size_t)z * T_LEN + rowBase + tid]);
    __syncthreads();

    float acc[8][4], compA[8][4], rsum[8], compR[8];
#pragma unroll
    for (int i = 0; i < 8; i++) {
        rsum[i] = 0.0f; compR[i] = 0.0f;
#pragma unroll
        for (int j = 0; j < 4; j++) { acc[i][j] = 0.0f; compA[i][j] = 0.0f; }
    }

    int srow0 = (tid + 0) >> 2, skq0 = (tid + 0) & 3;
    int srow1 = (tid + 256) >> 2, skq1 = (tid + 256) & 3;
    int vkr = tid >> 4, vn4 = tid & 15;

    // prologue: stage 0 loads
    float4 sv0 = *(const float4*)(Sp + (size_t)srow0 * T_LEN + skq0 * 4);
    float4 sv1 = *(const float4*)(Sp + (size_t)srow1 * T_LEN + skq1 * 4);
    float4 vv  = *(const float4*)(Vp + (size_t)vkr * D_MODEL + vn4 * 4);

    for (int k0 = 0; k0 < T_LEN; k0 += 16) {
        {
            float m0 = m_s[srow0];
            As[skq0 * 4 + 0][srow0] = expf(sv0.x - m0);
            As[skq0 * 4 + 1][srow0] = expf(sv0.y - m0);
            As[skq0 * 4 + 2][srow0] = expf(sv0.z - m0);
            As[skq0 * 4 + 3][srow0] = expf(sv0.w - m0);
            float m1 = m_s[srow1];
            As[skq1 * 4 + 0][srow1] = expf(sv1.x - m1);
            As[skq1 * 4 + 1][srow1] = expf(sv1.y - m1);
            As[skq1 * 4 + 2][srow1] = expf(sv1.z - m1);
            As[skq1 * 4 + 3][srow1] = expf(sv1.w - m1);
            *(float4*)&Bs[vkr][vn4 * 4] = vv;
        }
        __syncthreads();
        if (k0 + 16 < T_LEN) {          // prefetch next stage
            int kn = k0 + 16;
            sv0 = *(const float4*)(Sp + (size_t)srow0 * T_LEN + kn + skq0 * 4);
            sv1 = *(const float4*)(Sp + (size_t)srow1 * T_LEN + kn + skq1 * 4);
            vv  = *(const float4*)(Vp + (size_t)(kn + vkr) * D_MODEL + vn4 * 4);
        }
        float cacc[8][4], csum[8];
#pragma unroll
        for (int i = 0; i < 8; i++) {
            csum[i] = 0.0f;
#pragma unroll
            for (int j = 0; j < 4; j++) cacc[i][j] = 0.0f;
        }
#pragma unroll
        for (int kk = 0; kk < 16; kk++) {
            float4 a0 = *(float4*)&As[kk][ty * 4];
            float4 a1 = *(float4*)&As[kk][64 + ty * 4];
            float4 bv = *(float4*)&Bs[kk][tx * 4];
            float ar[8] = {a0.x, a0.y, a0.z, a0.w, a1.x, a1.y, a1.z, a1.w};
            float br[4] = {bv.x, bv.y, bv.z, bv.w};
#pragma unroll
            for (int i = 0; i < 8; i++) {
                csum[i] += ar[i];
#pragma unroll
                for (int j = 0; j < 4; j++)
                    cacc[i][j] = fmaf(ar[i], br[j], cacc[i][j]);
            }
        }
        // Kahan merge chunk sums into running totals
#pragma unroll
        for (int i = 0; i < 8; i++) {
            float yv = csum[i] - compR[i];
            float t = rsum[i] + yv;
            compR[i] = (t - rsum[i]) - yv;
            rsum[i] = t;
#pragma unroll
            for (int j = 0; j < 4; j++) {
                float ya = cacc[i][j] - compA[i][j];
                float ta = acc[i][j] + ya;
                compA[i][j] = (ta - acc[i][j]) - ya;
                acc[i][j] = ta;
            }
        }
        __syncthreads();
    }

#pragma unroll
    for (int i = 0; i < 8; i++) {
        int lr = (i < 4) ? (ty * 4 + i) : (64 + ty * 4 + i - 4);
        size_t orow = (size_t)(b * T_LEN + rowBase + lr) * D_MODEL + h * 64 + tx * 4;
        __half p1[4], p2[4], p3[4];
#pragma unroll
        for (int j = 0; j < 4; j++) split3s(acc[i][j] / rsum[i], p1[j], p2[j], p3[j]);
        *(uint2*)(g_O1 + orow) = make_uint2(packh2(p1[0], p1[1]), packh2(p1[2], p1[3]));
        *(uint2*)(g_O2 + orow) = make_uint2(packh2(p2[0], p2[1]), packh2(p2[2], p2[3]));
        *(uint2*)(g_O3 + orow) = make_uint2(packh2(p3[0], p3[1]), packh2(p3[2], p3[3]));
    }
}

// ---------------- fp4 quant ----------------
__global__ void k_absmax_partial(const float* __restrict__ Y) {
    __shared__ float sm[256];
    int base = blockIdx.x * 1024, tid = threadIdx.x;
    float m = 0.0f;
#pragma unroll
    for (int i = 0; i < 4; i++) m = fmaxf(m, fabsf(Y[base + tid + i * 256]));
    sm[tid] = m; __syncthreads();
    for (int st = 128; st > 0; st >>= 1) {
        if (tid < st) sm[tid] = fmaxf(sm[tid], sm[tid + st]);
        __syncthreads();
    }
    if (tid == 0) g_maxp[blockIdx.x] = sm[0];
}
__global__ void k_absmax_final() {
    __shared__ float sm[1024];
    int tid = threadIdx.x;
    float m = 0.0f;
#pragma unroll
    for (int i = 0; i < 4; i++) m = fmaxf(m, g_maxp[tid + i * 1024]);
    sm[tid] = m; __syncthreads();
    for (int st = 512; st > 0; st >>= 1) {
        if (tid < st) sm[tid] = fmaxf(sm[tid], sm[tid + st]);
        __syncthreads();
    }
    if (tid == 0) g_scale = fmaxf(sm[0] / 7.0f, 1e-8f);
}
__global__ void k_quant(const float* __restrict__ Y, float* __restrict__ out) {
    int i = blockIdx.x * 1024 + threadIdx.x;
    float s = g_scale;
    float q = rintf(Y[i] / s);
    out[i] = fminf(7.0f, fmaxf(-7.0f, q)) * s;
}

// ---------------- launch ----------------
extern "C" void kernel_launch(void* const* d_in, const int* in_sizes, int n_in,
                              void* d_out, int out_size) {
    const float* x  = (const float*)d_in[0];
    const float* Wq = (const float*)d_in[1];
    const float* bq = (const float*)d_in[2];
    const float* Wk = (const float*)d_in[3];
    const float* bk = (const float*)d_in[4];
    const float* Wv = (const float*)d_in[5];
    const float* bv = (const float*)d_in[6];
    const float* Wo = (const float*)d_in[7];
    const float* bo = (const float*)d_in[8];
    float* out = (float*)d_out;

    __half *tw, *x1, *x2, *x3, *q1, *q2, *q3, *kk1, *kk2, *kk3, *o1, *o2, *o3;
    float *v, *y;
    cudaGetSymbolAddress((void**)&tw, g_Tw);
    cudaGetSymbolAddress((void**)&x1, g_X1);  cudaGetSymbolAddress((void**)&x2, g_X2);
    cudaGetSymbolAddress((void**)&x3, g_X3);
    cudaGetSymbolAddress((void**)&q1, g_Q1);  cudaGetSymbolAddress((void**)&q2, g_Q2);
    cudaGetSymbolAddress((void**)&q3, g_Q3);
    cudaGetSymbolAddress((void**)&kk1, g_K1); cudaGetSymbolAddress((void**)&kk2, g_K2);
    cudaGetSymbolAddress((void**)&kk3, g_K3);
    cudaGetSymbolAddress((void**)&o1, g_O1);  cudaGetSymbolAddress((void**)&o2, g_O2);
    cudaGetSymbolAddress((void**)&o3, g_O3);
    cudaGetSymbolAddress((void**)&v, g_V);    cudaGetSymbolAddress((void**)&y, g_Y);

    cudaFuncSetAttribute(k_hproj, cudaFuncAttributeMaxDynamicSharedMemorySize, 32768);
    cudaFuncSetAttribute(k_hs, cudaFuncAttributeMaxDynamicSharedMemorySize, 98304);

    // 0-3) init + weight stats + alpha + ternarize (elementwise)
    k_rmax_init<<<64, 1024>>>();
    k_wabs<<<dim3(1024, 4), 256>>>(Wq, Wk, Wv, Wo);
    k_wmask<<<dim3(1024, 4), 256>>>(Wq, Wk, Wv, Wo);
    k_walpha<<<4, 1024>>>();
    k_wtern<<<dim3(1024, 4), 1024>>>(Wq, Wk, Wv, Wo);

    // 4) x -> scaled fp16 triple
    k_split3<<<4096, 1024>>>(x);

    // 5-7) projections (HMMA, reg double-buffered): Q,K -> fp16 triples; V -> fp32
    k_hproj<<<dim3(32, 8), 256, 32768>>>(x1, x2, x3, tw + 0 * (size_t)W_ELEMS, 0, bq,
                                         nullptr, q1, q2, q3, 1);
    k_hproj<<<dim3(32, 8), 256, 32768>>>(x1, x2, x3, tw + 1 * (size_t)W_ELEMS, 1, bk,
                                         nullptr, kk1, kk2, kk3, 1);
    k_hproj<<<dim3(32, 8), 256, 32768>>>(x1, x2, x3, tw + 2 * (size_t)W_ELEMS, 2, bv,
                                         v, nullptr, nullptr, nullptr, 0);

    // 8) S = QK^T/8 (grouped scaled cross-terms) + row max
    k_hs<<<dim3(16, 16, BATCH * N_HEADS), 256, 98304>>>();

    // 9) fused softmax + PV (two-level Kahan, reg-staged loads)
    k_pv<<<dim3(16, BATCH * N_HEADS), 256>>>();

    // 10) out projection -> Y fp32
    k_hproj<<<dim3(32, 8), 256, 32768>>>(o1, o2, o3, tw + 3 * (size_t)W_ELEMS, 3, bo,
                                         y, nullptr, nullptr, nullptr, 0);

    // 11-13) fp4 quant
    k_absmax_partial<<<4096, 256>>>(y);
    k_absmax_final<<<1, 1024>>>();
    k_quant<<<4096, 1024>>>(y, out);
}

// round 10
// speedup vs baseline: 1.6110x; 1.1296x over previous
#include <cuda_runtime.h>
#include <cuda_fp16.h>
#include <math.h>
#include <stdint.h>

#define D_MODEL 1024
#define T_LEN   2048
#define BATCH   2
#define N_HEADS 16
#define D_HEAD  64
#define BT      (BATCH * T_LEN)
#define W_ELEMS (D_MODEL * D_MODEL)

#define SPLIT_UP   2048.0f          // 2^11
#define SPLIT_UP2  4194304.0f       // 2^22
#define SPLIT_DN   4.8828125e-4f    // 2^-11

// ---------------- static scratch ----------------
__device__ __half g_Tw[4][W_ELEMS];
__device__ __half g_X1[BT * D_MODEL], g_X2[BT * D_MODEL], g_X3[BT * D_MODEL];
__device__ __half g_Q1[BT * D_MODEL], g_Q2[BT * D_MODEL], g_Q3[BT * D_MODEL];
__device__ __half g_K1[BT * D_MODEL], g_K2[BT * D_MODEL], g_K3[BT * D_MODEL];
__device__ float  g_V[BT * D_MODEL];
__device__ __half g_Vt1[BT * D_MODEL], g_Vt2[BT * D_MODEL], g_Vt3[BT * D_MODEL]; // [b][dim][token]
__device__ __half g_O1[BT * D_MODEL], g_O2[BT * D_MODEL], g_O3[BT * D_MODEL];
__device__ float  g_Y[BT * D_MODEL];
__device__ float  g_S[(size_t)BATCH * N_HEADS * T_LEN * T_LEN];   // 512 MB
__device__ unsigned g_rmax[BATCH * N_HEADS * T_LEN];
__device__ double g_red[4][1024], g_red2a[4][1024], g_red2b[4][1024];
__device__ float  g_delta[4], g_alphaf[4], g_maxp[4096], g_scale;

// ---------------- helpers ----------------
__device__ __forceinline__ uint32_t smem_u32(const void* p) {
    uint32_t a;
    asm("{ .reg .u64 t; cvta.to.shared.u64 t, %1; cvt.u32.u64 %0, t; }" : "=r"(a) : "l"(p));
    return a;
}
__device__ __forceinline__ void ldsm4(uint32_t (&r)[4], uint32_t addr) {
    asm volatile("ldmatrix.sync.aligned.m8n8.x4.shared.b16 {%0,%1,%2,%3}, [%4];"
                 : "=r"(r[0]), "=r"(r[1]), "=r"(r[2]), "=r"(r[3]) : "r"(addr));
}
__device__ __forceinline__ void mma16816(float (&d)[4], const uint32_t (&a)[4],
                                         uint32_t b0, uint32_t b1) {
    asm volatile("mma.sync.aligned.m16n8k16.row.col.f32.f16.f16.f32 "
                 "{%0,%1,%2,%3}, {%4,%5,%6,%7}, {%8,%9}, {%0,%1,%2,%3};"
                 : "+f"(d[0]), "+f"(d[1]), "+f"(d[2]), "+f"(d[3])
                 : "r"(a[0]), "r"(a[1]), "r"(a[2]), "r"(a[3]), "r"(b0), "r"(b1));
}
__device__ __forceinline__ unsigned fenc(float f) {
    unsigned b = __float_as_uint(f);
    return (b & 0x80000000u) ? ~b : (b | 0x80000000u);
}
__device__ __forceinline__ float fdec(unsigned u) {
    unsigned b = (u & 0x80000000u) ? (u & 0x7FFFFFFFu) : ~u;
    return __uint_as_float(b);
}
__device__ __forceinline__ void split3s(float y, __half& p1, __half& p2, __half& p3) {
    p1 = __float2half_rn(y);
    float r = y - __half2float(p1);
    p2 = __float2half_rn(r * SPLIT_UP);
    float r2 = r - __half2float(p2) * SPLIT_DN;
    p3 = __float2half_rn(r2 * SPLIT_UP2);
}
__device__ __forceinline__ uint32_t packh2(__half a, __half b) {
    __half2 h = __halves2half2(a, b);
    return *(uint32_t*)&h;
}

// ---------------- weight stats (exact doubles, unchanged) ----------------
__device__ __forceinline__ const float* pick_w(const float* W0, const float* W1,
                                               const float* W2, const float* W3, int y) {
    return y == 0 ? W0 : (y == 1 ? W1 : (y == 2 ? W2 : W3));
}
__global__ void k_rmax_init() { g_rmax[blockIdx.x * 1024 + threadIdx.x] = 0u; }

__global__ void k_wabs(const float* __restrict__ W0, const float* __restrict__ W1,
                       const float* __restrict__ W2, const float* __restrict__ W3) {
    const float* W = pick_w(W0, W1, W2, W3, blockIdx.y);
    __shared__ double sm[256];
    int base = blockIdx.x * 1024;
    double s = 0.0;
    for (int i = threadIdx.x; i < 1024; i += 256) s += (double)fabsf(W[base + i]);
    sm[threadIdx.x] = s; __syncthreads();
    for (int st = 128; st > 0; st >>= 1) {
        if (threadIdx.x < st) sm[threadIdx.x] += sm[threadIdx.x + st];
        __syncthreads();
    }
    if (threadIdx.x == 0) g_red[blockIdx.y][blockIdx.x] = sm[0];
}
__global__ void k_wmask(const float* __restrict__ W0, const float* __restrict__ W1,
                        const float* __restrict__ W2, const float* __restrict__ W3) {
    int y = blockIdx.y;
    const float* W = pick_w(W0, W1, W2, W3, y);
    __shared__ double sa[256], sb[256];
    double s = 0.0;
    for (int i = threadIdx.x; i < 1024; i += 256) s += g_red[y][i];
    sa[threadIdx.x] = s; __syncthreads();
    for (int st = 128; st > 0; st >>= 1) {
        if (threadIdx.x < st) sa[threadIdx.x] += sa[threadIdx.x + st];
        __syncthreads();
    }
    float delta = (float)(0.05 * (sa[0] / (double)W_ELEMS));
    if (blockIdx.x == 0 && threadIdx.x == 0) g_delta[y] = delta;
    __syncthreads();
    int base = blockIdx.x * 1024;
    double s1 = 0.0, s2 = 0.0;
    for (int i = threadIdx.x; i < 1024; i += 256) {
        float a = fabsf(W[base + i]);
        if (a > delta) { s1 += (double)a; s2 += 1.0; }
    }
    sa[threadIdx.x] = s1; sb[threadIdx.x] = s2; __syncthreads();
    for (int st = 128; st > 0; st >>= 1) {
        if (threadIdx.x < st) { sa[threadIdx.x] += sa[threadIdx.x + st]; sb[threadIdx.x] += sb[threadIdx.x + st]; }
        __syncthreads();
    }
    if (threadIdx.x == 0) { g_red2a[y][blockIdx.x] = sa[0]; g_red2b[y][blockIdx.x] = sb[0]; }
}
__global__ void k_walpha() {
    int y = blockIdx.x;
    __shared__ double sa[1024], sb[1024];
    sa[threadIdx.x] = g_red2a[y][threadIdx.x];
    sb[threadIdx.x] = g_red2b[y][threadIdx.x];
    __syncthreads();
    for (int st = 512; st > 0; st >>= 1) {
        if (threadIdx.x < st) { sa[threadIdx.x] += sa[threadIdx.x + st]; sb[threadIdx.x] += sb[threadIdx.x + st]; }
        __syncthreads();
    }
    if (threadIdx.x == 0) g_alphaf[y] = (float)(sa[0] / fmax(sb[0], 1.0));
}
__global__ void k_wtern(const float* __restrict__ W0, const float* __restrict__ W1,
                        const float* __restrict__ W2, const float* __restrict__ W3) {
    int y = blockIdx.y;
    const float* W = pick_w(W0, W1, W2, W3, y);
    float delta = g_delta[y];
    int i = blockIdx.x * 1024 + threadIdx.x;
    float w = W[i];
    float t = (fabsf(w) > delta) ? ((w > 0.0f) ? 1.0f : -1.0f) : 0.0f;
    g_Tw[y][i] = __float2half_rn(t);
}

__global__ void k_split3(const float* __restrict__ X) {
    int i = blockIdx.x * 1024 + threadIdx.x;
    __half p1, p2, p3;
    split3s(X[i], p1, p2, p3);
    g_X1[i] = p1; g_X2[i] = p2; g_X3[i] = p3;
}

// ---------------- tile staging (lda-parametrized) ----------------
struct TileRegs { uint4 v[4]; };
__device__ __forceinline__ void tile_ldg(TileRegs& r, const __half* __restrict__ g,
                                         int row0, int col0, int lda) {
    int tid = threadIdx.x;
#pragma unroll
    for (int i = 0; i < 4; i++) {
        int idx = tid + i * 256;
        int row = idx >> 3, c = idx & 7;
        r.v[i] = *(const uint4*)(g + (size_t)(row0 + row) * lda + col0 + c * 8);
    }
}
__device__ __forceinline__ void tile_sts(__half* s, const TileRegs& r) {
    int tid = threadIdx.x;
#pragma unroll
    for (int i = 0; i < 4; i++) {
        int idx = tid + i * 256;
        int row = idx >> 3, c = idx & 7;
        int cs = c ^ (row & 7);
        *(uint4*)((char*)s + row * 128 + cs * 16) = r.v[i];
    }
}
__device__ __forceinline__ void load_tile_h(__half* s, const __half* __restrict__ g,
                                            int row0, int col0, int lda) {
    TileRegs r;
    tile_ldg(r, g, row0, col0, lda);
    tile_sts(s, r);
}

// one BK=64 stage of 128x128 HMMA; warp (wm,wn) owns 64x32
__device__ __forceinline__ void hgemm_core(uint32_t aB, uint32_t bB, int wm, int wn,
                                           int lane, float (&acc)[4][4][4]) {
#pragma unroll
    for (int kf = 0; kf < 4; kf++) {
        uint32_t a[4][4];
#pragma unroll
        for (int i = 0; i < 4; i++) {
            int row = wm * 64 + i * 16 + (lane & 15);
            int ch = (kf * 2 + (lane >> 4)) ^ (row & 7);
            ldsm4(a[i], aB + (uint32_t)(row * 8 + ch) * 16);
        }
        uint32_t b[4][2];
#pragma unroll
        for (int jp = 0; jp < 2; jp++) {
            int nrow = wn * 32 + jp * 16 + (lane & 7) + ((lane >> 4) << 3);
            int ch = (kf * 2 + ((lane >> 3) & 1)) ^ (nrow & 7);
            uint32_t t[4];
            ldsm4(t, bB + (uint32_t)(nrow * 8 + ch) * 16);
            b[jp * 2][0] = t[0]; b[jp * 2][1] = t[1];
            b[jp * 2 + 1][0] = t[2]; b[jp * 2 + 1][1] = t[3];
        }
#pragma unroll
        for (int i = 0; i < 4; i++)
#pragma unroll
            for (int j = 0; j < 4; j++)
                mma16816(acc[i][j], a[i], b[j][0], b[j][1]);
    }
}
__device__ __forceinline__ void acc_scale(float (&acc)[4][4][4], float s) {
#pragma unroll
    for (int i = 0; i < 4; i++)
#pragma unroll
        for (int j = 0; j < 4; j++)
#pragma unroll
            for (int q = 0; q < 4; q++) acc[i][j][q] *= s;
}

// BK=64 stage of 128x64 HMMA; warp: wm=w>>1 owns 32 rows (2 m16), wn=w&1 owns 32 cols (4 n8)
__device__ __forceinline__ void hgemm64(uint32_t aB, uint32_t bB, int wm, int wn,
                                        int lane, float (&acc)[2][4][4]) {
#pragma unroll
    for (int kf = 0; kf < 4; kf++) {
        uint32_t a[2][4];
#pragma unroll
        for (int i = 0; i < 2; i++) {
            int row = wm * 32 + i * 16 + (lane & 15);
            int ch = (kf * 2 + (lane >> 4)) ^ (row & 7);
            ldsm4(a[i], aB + (uint32_t)(row * 8 + ch) * 16);
        }
        uint32_t b[4][2];
#pragma unroll
        for (int jp = 0; jp < 2; jp++) {
            int nrow = wn * 32 + jp * 16 + (lane & 7) + ((lane >> 4) << 3);
            int ch = (kf * 2 + ((lane >> 3) & 1)) ^ (nrow & 7);
            uint32_t t[4];
            ldsm4(t, bB + (uint32_t)(nrow * 8 + ch) * 16);
            b[jp * 2][0] = t[0]; b[jp * 2][1] = t[1];
            b[jp * 2 + 1][0] = t[2]; b[jp * 2 + 1][1] = t[3];
        }
#pragma unroll
        for (int i = 0; i < 2; i++)
#pragma unroll
            for (int j = 0; j < 4; j++)
                mma16816(acc[i][j], a[i], b[j][0], b[j][1]);
    }
}

// ---------------- generic projection body (reg double-buffered) ----------------
__device__ __forceinline__ void hproj_body(
        const __half* __restrict__ A0, const __half* __restrict__ A1,
        const __half* __restrict__ A2, const __half* __restrict__ Bw, int widx,
        const float* __restrict__ bias, float* __restrict__ outF,
        __half* __restrict__ O1, __half* __restrict__ O2, __half* __restrict__ O3,
        int mode, __half* sA, __half* sB) {
    int tid = threadIdx.x, lane = tid & 31, w = tid >> 5, wm = w >> 2, wn = w & 3;
    int m0 = blockIdx.x * 128, n0 = blockIdx.y * 128;
    float acc[4][4][4];
#pragma unroll
    for (int i = 0; i < 4; i++)
#pragma unroll
        for (int j = 0; j < 4; j++)
#pragma unroll
            for (int q = 0; q < 4; q++) acc[i][j][q] = 0.0f;
    uint32_t aB = smem_u32(sA), bB = smem_u32(sB);

    const __half* As3[3] = {A2, A1, A0};   // smallest scale first (Horner)
    TileRegs ra, rb;
    tile_ldg(ra, As3[0], m0, 0, D_MODEL);
    tile_ldg(rb, Bw, n0, 0, D_MODEL);

    for (int st = 0; st < 48; st++) {
        __syncthreads();
        tile_sts(sA, ra);
        tile_sts(sB, rb);
        __syncthreads();
        if (st < 47) {
            int nst = st + 1;
            tile_ldg(ra, As3[nst >> 4], m0, (nst & 15) * 64, D_MODEL);
            tile_ldg(rb, Bw, n0, (nst & 15) * 64, D_MODEL);
        }
        hgemm_core(aB, bB, wm, wn, lane, acc);
        if (st == 15 || st == 31) acc_scale(acc, SPLIT_DN);
    }

    float alpha = g_alphaf[widx];
    int gid = lane >> 2, tid2 = lane & 3;
#pragma unroll
    for (int i = 0; i < 4; i++) {
#pragma unroll
        for (int j = 0; j < 4; j++) {
            int row = m0 + wm * 64 + i * 16 + gid;
            int col = n0 + wn * 32 + j * 8 + tid2 * 2;
            float b0 = bias[col], b1 = bias[col + 1];
            float y00 = acc[i][j][0] * alpha + b0, y01 = acc[i][j][1] * alpha + b1;
            float y10 = acc[i][j][2] * alpha + b0, y11 = acc[i][j][3] * alpha + b1;
            if (mode == 0) {
                *(float2*)(outF + (size_t)row * D_MODEL + col) = make_float2(y00, y01);
                *(float2*)(outF + (size_t)(row + 8) * D_MODEL + col) = make_float2(y10, y11);
            } else {
                __half u1, u2, u3, v1, v2, v3;
                size_t r0 = (size_t)row * D_MODEL + col;
                size_t r1 = (size_t)(row + 8) * D_MODEL + col;
                split3s(y00, u1, u2, u3); split3s(y01, v1, v2, v3);
                *(uint32_t*)(O1 + r0) = packh2(u1, v1);
                *(uint32_t*)(O2 + r0) = packh2(u2, v2);
                *(uint32_t*)(O3 + r0) = packh2(u3, v3);
                split3s(y10, u1, u2, u3); split3s(y11, v1, v2, v3);
                *(uint32_t*)(O1 + r1) = packh2(u1, v1);
                *(uint32_t*)(O2 + r1) = packh2(u2, v2);
                *(uint32_t*)(O3 + r1) = packh2(u3, v3);
            }
        }
    }
}

// merged Q/K/V projection: z selects weight/bias/output
__global__ void __launch_bounds__(256)
k_hproj_qkv(const __half* __restrict__ x1, const __half* __restrict__ x2,
            const __half* __restrict__ x3, const __half* __restrict__ tw,
            const float* __restrict__ bq, const float* __restrict__ bk,
            const float* __restrict__ bv, float* __restrict__ vout,
            __half* __restrict__ q1, __half* __restrict__ q2, __half* __restrict__ q3,
            __half* __restrict__ kk1, __half* __restrict__ kk2, __half* __restrict__ kk3) {
    extern __shared__ __align__(16) __half smp[];
    int z = blockIdx.z;
    const __half* Bw = tw + (size_t)z * W_ELEMS;
    const float* bias = (z == 0) ? bq : (z == 1 ? bk : bv);
    if (z == 2)
        hproj_body(x1, x2, x3, Bw, 2, bias, vout, nullptr, nullptr, nullptr, 0, smp, smp + 8192);
    else if (z == 0)
        hproj_body(x1, x2, x3, Bw, 0, bias, nullptr, q1, q2, q3, 1, smp, smp + 8192);
    else
        hproj_body(x1, x2, x3, Bw, 1, bias, nullptr, kk1, kk2, kk3, 1, smp, smp + 8192);
}

// out projection (mode 0)
__global__ void __launch_bounds__(256)
k_hproj(const __half* __restrict__ A0, const __half* __restrict__ A1,
        const __half* __restrict__ A2, const __half* __restrict__ Bw, int widx,
        const float* __restrict__ bias, float* __restrict__ outF) {
    extern __shared__ __align__(16) __half smp[];
    hproj_body(A0, A1, A2, Bw, widx, bias, outF, nullptr, nullptr, nullptr, 0, smp, smp + 8192);
}

// ---------------- V transpose + split: g_V[b][t][d] -> g_Vt{1,2,3}[b][d][t] ----------------
__global__ void __launch_bounds__(256)
k_vsplitT() {
    __shared__ float sT[64][65];
    int t0 = blockIdx.x * 64, d0 = blockIdx.y * 64, b = blockIdx.z;
    int tid = threadIdx.x;
    const float* V = g_V + ((size_t)b * T_LEN) * D_MODEL;
#pragma unroll
    for (int i = 0; i < 4; i++) {
        int idx4 = tid + i * 256;                 // 0..1023 float4 slots
        int tok = idx4 >> 4, c4 = idx4 & 15;
        float4 v = *(const float4*)(V + (size_t)(t0 + tok) * D_MODEL + d0 + c4 * 4);
        sT[tok][c4 * 4 + 0] = v.x;
        sT[tok][c4 * 4 + 1] = v.y;
        sT[tok][c4 * 4 + 2] = v.z;
        sT[tok][c4 * 4 + 3] = v.w;
    }
    __syncthreads();
    int d = tid >> 2, chunk = tid & 3;            // 64 dims x 4 chunks of 16 tokens
    __half h1[16], h2[16], h3[16];
#pragma unroll
    for (int j = 0; j < 16; j++)
        split3s(sT[chunk * 16 + j][d], h1[j], h2[j], h3[j]);
    size_t base = ((size_t)b * D_MODEL + d0 + d) * T_LEN + t0 + chunk * 16;
    *(uint4*)(g_Vt1 + base) = *(uint4*)&h1[0];
    *(uint4*)(g_Vt1 + base + 8) = *(uint4*)&h1[8];
    *(uint4*)(g_Vt2 + base) = *(uint4*)&h2[0];
    *(uint4*)(g_Vt2 + base + 8) = *(uint4*)&h2[8];
    *(uint4*)(g_Vt3 + base) = *(uint4*)&h3[0];
    *(uint4*)(g_Vt3 + base + 8) = *(uint4*)&h3[8];
}

// ---------------- S = (QK^T)/8 (unchanged numerics) ----------------
__global__ void __launch_bounds__(256)
k_hs() {
    extern __shared__ __align__(16) __half sms[];
    __half* sQ[3] = {sms, sms + 8192, sms + 16384};
    __half* sK[3] = {sms + 24576, sms + 32768, sms + 40960};

    int tid = threadIdx.x, lane = tid & 31, w = tid >> 5, wm = w >> 2, wn = w & 3;
    int z = blockIdx.z, b = z >> 4, h = z & 15;
    int arow0 = b * T_LEN + blockIdx.x * 128;
    int brow0 = b * T_LEN + blockIdx.y * 128;
    int col0 = h * 64;
    float acc[4][4][4];
#pragma unroll
    for (int i = 0; i < 4; i++)
#pragma unroll
        for (int j = 0; j < 4; j++)
#pragma unroll
            for (int q = 0; q < 4; q++) acc[i][j][q] = 0.0f;

    load_tile_h(sQ[0], g_Q1, arow0, col0, D_MODEL);
    load_tile_h(sQ[1], g_Q2, arow0, col0, D_MODEL);
    load_tile_h(sQ[2], g_Q3, arow0, col0, D_MODEL);
    load_tile_h(sK[0], g_K1, brow0, col0, D_MODEL);
    load_tile_h(sK[1], g_K2, brow0, col0, D_MODEL);
    load_tile_h(sK[2], g_K3, brow0, col0, D_MODEL);
    __syncthreads();

    uint32_t qB[3] = {smem_u32(sQ[0]), smem_u32(sQ[1]), smem_u32(sQ[2])};
    uint32_t kB[3] = {smem_u32(sK[0]), smem_u32(sK[1]), smem_u32(sK[2])};
    hgemm_core(qB[1], kB[1], wm, wn, lane, acc);
    hgemm_core(qB[0], kB[2], wm, wn, lane, acc);
    hgemm_core(qB[2], kB[0], wm, wn, lane, acc);
    acc_scale(acc, SPLIT_DN);
    hgemm_core(qB[0], kB[1], wm, wn, lane, acc);
    hgemm_core(qB[1], kB[0], wm, wn, lane, acc);
    acc_scale(acc, SPLIT_DN);
    hgemm_core(qB[0], kB[0], wm, wn, lane, acc);

    int gid = lane >> 2, tid2 = lane & 3;
    size_t zrow = (size_t)z * T_LEN;
#pragma unroll
    for (int i = 0; i < 4; i++) {
        int rl0 = blockIdx.x * 128 + wm * 64 + i * 16 + gid;
        float m0v = -INFINITY, m1v = -INFINITY;
#pragma unroll
        for (int j = 0; j < 4; j++) {
            int col = blockIdx.y * 128 + wn * 32 + j * 8 + tid2 * 2;
            float y00 = acc[i][j][0] * 0.125f, y01 = acc[i][j][1] * 0.125f;
            float y10 = acc[i][j][2] * 0.125f, y11 = acc[i][j][3] * 0.125f;
            *(float2*)(g_S + (zrow + rl0) * T_LEN + col) = make_float2(y00, y01);
            *(float2*)(g_S + (zrow + rl0 + 8) * T_LEN + col) = make_float2(y10, y11);
            m0v = fmaxf(m0v, fmaxf(y00, y01));
            m1v = fmaxf(m1v, fmaxf(y10, y11));
        }
        atomicMax(&g_rmax[zrow + rl0], fenc(m0v));
        atomicMax(&g_rmax[zrow + rl0 + 8], fenc(m1v));
    }
}

// ---- HMMA softmax+PV: O = softmax(S) @ V via scaled fp16 cross terms ----
// smem: P0/P1/P2 128x64 tiles (16KB ea), V0/V1/V2 64x64 tiles (8KB ea) = 72KB dyn
__global__ void __launch_bounds__(256)
k_pvh() {
    extern __shared__ __align__(16) __half smv[];
    __half* sP0 = smv;
    __half* sP1 = (__half*)((char*)smv + 16384);
    __half* sP2 = (__half*)((char*)smv + 32768);
    __half* sV0 = (__half*)((char*)smv + 49152);
    __half* sV1 = (__half*)((char*)smv + 57344);
    __half* sV2 = (__half*)((char*)smv + 65536);
    __shared__ float m_s[128];
    __shared__ float rs2[256];
    __shared__ float rsum_s[128];

    int tid = threadIdx.x, lane = tid & 31, w = tid >> 5;
    int wm = w >> 1, wn = w & 1;
    int z = blockIdx.y, b = z >> 4, h = z & 15;
    int rowBase = blockIdx.x * 128;
    const float* Sp = g_S + ((size_t)z * T_LEN + rowBase) * T_LEN;
    size_t vbase = (size_t)b * D_MODEL + h * 64;

    if (tid < 128) m_s[tid] = fdec(g_rmax[(size_t)z * T_LEN + rowBase + tid]);
    __syncthreads();

    float acc[2][4][4], compA[2][4][4];
#pragma unroll
    for (int i = 0; i < 2; i++)
#pragma unroll
        for (int j = 0; j < 4; j++)
#pragma unroll
            for (int q = 0; q < 4; q++) { acc[i][j][q] = 0.0f; compA[i][j][q] = 0.0f; }
    float rs = 0.0f, rcomp = 0.0f;

    int prow = tid >> 1;                 // 0..127
    int pcb = (tid & 1) * 32;            // col base 0 or 32
    float pm = m_s[prow];
    uint32_t aP0 = smem_u32(sP0), aP1 = smem_u32(sP1), aP2 = smem_u32(sP2);
    uint32_t bV0 = smem_u32(sV0), bV1 = smem_u32(sV1), bV2 = smem_u32(sV2);

    for (int k0 = 0; k0 < T_LEN; k0 += 64) {
        __syncthreads();                 // smem free from previous stage's MMAs
        float csum = 0.0f;
        // P tiles: exp + split3 + swizzled STS (32 cols per thread, 4 chunks of 8)
#pragma unroll
        for (int cc = 0; cc < 4; cc++) {
            int colb = pcb + cc * 8;
            float4 v0 = *(const float4*)(Sp + (size_t)prow * T_LEN + k0 + colb);
            float4 v1 = *(const float4*)(Sp + (size_t)prow * T_LEN + k0 + colb + 4);
            float e[8] = {expf(v0.x - pm), expf(v0.y - pm), expf(v0.z - pm), expf(v0.w - pm),
                          expf(v1.x - pm), expf(v1.y - pm), expf(v1.z - pm), expf(v1.w - pm)};
#pragma unroll
            for (int q = 0; q < 8; q++) csum += e[q];
            __half h1[8], h2[8], h3[8];
#pragma unroll
            for (int q = 0; q < 8; q++) split3s(e[q], h1[q], h2[q], h3[q]);
            int c16 = colb >> 3;
            int cs = c16 ^ (prow & 7);
            uint32_t off = (uint32_t)prow * 128 + cs * 16;
            *(uint4*)((char*)sP0 + off) = *(uint4*)&h1[0];
            *(uint4*)((char*)sP1 + off) = *(uint4*)&h2[0];
            *(uint4*)((char*)sP2 + off) = *(uint4*)&h3[0];
        }
        // Kahan merge stage csum
        {
            float yv = csum - rcomp;
            float t = rs + yv;
            rcomp = (t - rs) - yv;
            rs = t;
        }
        // V tiles: 64 rows x 64 halfs each, from transposed splits
#pragma unroll
        for (int t = 0; t < 2; t++) {
            int idx = tid + t * 256;
            int vrow = idx >> 3, c = idx & 7;
            size_t src = (vbase + vrow) * T_LEN + k0 + c * 8;
            int cs = c ^ (vrow & 7);
            uint32_t off = (uint32_t)vrow * 128 + cs * 16;
            *(uint4*)((char*)sV0 + off) = *(const uint4*)(g_Vt1 + src);
            *(uint4*)((char*)sV1 + off) = *(const uint4*)(g_Vt2 + src);
            *(uint4*)((char*)sV2 + off) = *(const uint4*)(g_Vt3 + src);
        }
        __syncthreads();
        // fresh per-stage accumulator, Horner over scale groups
        float cacc[2][4][4];
#pragma unroll
        for (int i = 0; i < 2; i++)
#pragma unroll
            for (int j = 0; j < 4; j++)
#pragma unroll
                for (int q = 0; q < 4; q++) cacc[i][j][q] = 0.0f;
        hgemm64(aP0, bV2, wm, wn, lane, cacc);   // g2
        hgemm64(aP1, bV1, wm, wn, lane, cacc);
        hgemm64(aP2, bV0, wm, wn, lane, cacc);
#pragma unroll
        for (int i = 0; i < 2; i++)
#pragma unroll
            for (int j = 0; j < 4; j++)
#pragma unroll
                for (int q = 0; q < 4; q++) cacc[i][j][q] *= SPLIT_DN;
        hgemm64(aP0, bV1, wm, wn, lane, cacc);   // g1
        hgemm64(aP1, bV0, wm, wn, lane, cacc);
#pragma unroll
        for (int i = 0; i < 2; i++)
#pragma unroll
            for (int j = 0; j < 4; j++)
#pragma unroll
                for (int q = 0; q < 4; q++) cacc[i][j][q] *= SPLIT_DN;
        hgemm64(aP0, bV0, wm, wn, lane, cacc);   // g0
        // Kahan merge into running acc
#pragma unroll
        for (int i = 0; i < 2; i++)
#pragma unroll
            for (int j = 0; j < 4; j++)
#pragma unroll
                for (int q = 0; q < 4; q++) {
                    float ya = cacc[i][j][q] - compA[i][j][q];
                    float ta = acc[i][j][q] + ya;
                    compA[i][j][q] = (ta - acc[i][j][q]) - ya;
                    acc[i][j][q] = ta;
                }
    }

    // finalize rsum per row (two half-row partials)
    rs2[tid] = rs;
    __syncthreads();
    if (tid < 128) rsum_s[tid] = rs2[tid * 2] + rs2[tid * 2 + 1];
    __syncthreads();

    int gid = lane >> 2, tid2 = lane & 3;
#pragma unroll
    for (int i = 0; i < 2; i++) {
        int rl0 = wm * 32 + i * 16 + gid;        // local rows rl0, rl0+8
#pragma unroll
        for (int rr = 0; rr < 2; rr++) {
            int rl = rl0 + rr * 8;
            float inv_den = rsum_s[rl];
            size_t orow = (size_t)(b * T_LEN + rowBase + rl) * D_MODEL + h * 64;
#pragma unroll
            for (int j = 0; j < 4; j++) {
                int col = wn * 32 + j * 8 + tid2 * 2;
                float y0 = acc[i][j][rr * 2 + 0] / inv_den;
                float y1 = acc[i][j][rr * 2 + 1] / inv_den;
                __half u1, u2, u3, v1, v2, v3;
                split3s(y0, u1, u2, u3); split3s(y1, v1, v2, v3);
                *(uint32_t*)(g_O1 + orow + col) = packh2(u1, v1);
                *(uint32_t*)(g_O2 + orow + col) = packh2(u2, v2);
                *(uint32_t*)(g_O3 + orow + col) = packh2(u3, v3);
            }
        }
    }
}

// ---------------- fp4 quant ----------------
__global__ void k_absmax_partial(const float* __restrict__ Y) {
    __shared__ float sm[256];
    int base = blockIdx.x * 1024, tid = threadIdx.x;
    float m = 0.0f;
#pragma unroll
    for (int i = 0; i < 4; i++) m = fmaxf(m, fabsf(Y[base + tid + i * 256]));
    sm[tid] = m; __syncthreads();
    for (int st = 128; st > 0; st >>= 1) {
        if (tid < st) sm[tid] = fmaxf(sm[tid], sm[tid + st]);
        __syncthreads();
    }
    if (tid == 0) g_maxp[blockIdx.x] = sm[0];
}
__global__ void k_absmax_final() {
    __shared__ float sm[1024];
    int tid = threadIdx.x;
    float m = 0.0f;
#pragma unroll
    for (int i = 0; i < 4; i++) m = fmaxf(m, g_maxp[tid + i * 1024]);
    sm[tid] = m; __syncthreads();
    for (int st = 512; st > 0; st >>= 1) {
        if (tid < st) sm[tid] = fmaxf(sm[tid], sm[tid + st]);
        __syncthreads();
    }
    if (tid == 0) g_scale = fmaxf(sm[0] / 7.0f, 1e-8f);
}
__global__ void k_quant(const float* __restrict__ Y, float* __restrict__ out) {
    int i = blockIdx.x * 1024 + threadIdx.x;
    float s = g_scale;
    float q = rintf(Y[i] / s);
    out[i] = fminf(7.0f, fmaxf(-7.0f, q)) * s;
}

// ---------------- launch ----------------
extern "C" void kernel_launch(void* const* d_in, const int* in_sizes, int n_in,
                              void* d_out, int out_size) {
    const float* x  = (const float*)d_in[0];
    const float* Wq = (const float*)d_in[1];
    const float* bq = (const float*)d_in[2];
    const float* Wk = (const float*)d_in[3];
    const float* bk = (const float*)d_in[4];
    const float* Wv = (const float*)d_in[5];
    const float* bv = (const float*)d_in[6];
    const float* Wo = (const float*)d_in[7];
    const float* bo = (const float*)d_in[8];
    float* out = (float*)d_out;

    __half *tw, *x1, *x2, *x3, *q1, *q2, *q3, *kk1, *kk2, *kk3, *o1, *o2, *o3;
    float *v, *y;
    cudaGetSymbolAddress((void**)&tw, g_Tw);
    cudaGetSymbolAddress((void**)&x1, g_X1);  cudaGetSymbolAddress((void**)&x2, g_X2);
    cudaGetSymbolAddress((void**)&x3, g_X3);
    cudaGetSymbolAddress((void**)&q1, g_Q1);  cudaGetSymbolAddress((void**)&q2, g_Q2);
    cudaGetSymbolAddress((void**)&q3, g_Q3);
    cudaGetSymbolAddress((void**)&kk1, g_K1); cudaGetSymbolAddress((void**)&kk2, g_K2);
    cudaGetSymbolAddress((void**)&kk3, g_K3);
    cudaGetSymbolAddress((void**)&o1, g_O1);  cudaGetSymbolAddress((void**)&o2, g_O2);
    cudaGetSymbolAddress((void**)&o3, g_O3);
    cudaGetSymbolAddress((void**)&v, g_V);    cudaGetSymbolAddress((void**)&y, g_Y);

    cudaFuncSetAttribute(k_hproj_qkv, cudaFuncAttributeMaxDynamicSharedMemorySize, 32768);
    cudaFuncSetAttribute(k_hproj, cudaFuncAttributeMaxDynamicSharedMemorySize, 32768);
    cudaFuncSetAttribute(k_hs, cudaFuncAttributeMaxDynamicSharedMemorySize, 98304);
    cudaFuncSetAttribute(k_pvh, cudaFuncAttributeMaxDynamicSharedMemorySize, 73728);

    // 0-3) init + weight stats + alpha + ternarize
    k_rmax_init<<<64, 1024>>>();
    k_wabs<<<dim3(1024, 4), 256>>>(Wq, Wk, Wv, Wo);
    k_wmask<<<dim3(1024, 4), 256>>>(Wq, Wk, Wv, Wo);
    k_walpha<<<4, 1024>>>();
    k_wtern<<<dim3(1024, 4), 1024>>>(Wq, Wk, Wv, Wo);

    // 4) x -> scaled fp16 triple
    k_split3<<<4096, 1024>>>(x);

    // 5) merged Q/K/V projections (768 CTAs)
    k_hproj_qkv<<<dim3(32, 8, 3), 256, 32768>>>(x1, x2, x3, tw, bq, bk, bv, v,
                                                q1, q2, q3, kk1, kk2, kk3);

    // 6) V -> transposed scaled fp16 triple
    k_vsplitT<<<dim3(32, 16, 2), 256>>>();

    // 7) S = QK^T/8 + row max
    k_hs<<<dim3(16, 16, BATCH * N_HEADS), 256, 98304>>>();

    // 8) HMMA softmax+PV -> scaled fp16 triples
    k_pvh<<<dim3(16, BATCH * N_HEADS), 256, 73728>>>();

    // 9) out projection -> Y fp32
    k_hproj<<<dim3(32, 8), 256, 32768>>>(o1, o2, o3, tw + 3 * (size_t)W_ELEMS, 3, bo, y);

    // 10-12) fp4 quant
    k_absmax_partial<<<4096, 256>>>(y);
    k_absmax_final<<<1, 1024>>>();
    k_quant<<<4096, 1024>>>(y, out);
}